// round 1
// baseline (speedup 1.0000x reference)
#include <cuda_runtime.h>
#include <cuda_bf16.h>
#include <cstddef>
#include <cstdint>

// ============================================================================
// SmalldeckClassificationFlat — restructured:
//   prep:  parse+sort cards, gather embeddings -> heroIn[M][6][128], boardIn[M][10][192]
//   fold:  Wfold[2048][512] = grouped sums of oW1 slices (combo c = 10h+b)
//   GEMMs: hero 128->512->128, board 192->512->128 (written into X[M][2048]),
//          o1: X @ Wfold (K=2048), o2, o3, final scorer.
// All fp32. ~7.2e9 MACs total (vs 5.2e10 naive).
// ============================================================================

#define EMBD 64
static constexpr int MAXM = 2048;

// scratch layout (floats)
static constexpr size_t OFF_HEROIN  = 0;                                   // 2048*6*128
static constexpr size_t SZ_HEROIN   = (size_t)MAXM * 6 * 128;
static constexpr size_t OFF_BOARDIN = OFF_HEROIN + SZ_HEROIN;              // 2048*10*192
static constexpr size_t SZ_BOARDIN  = (size_t)MAXM * 10 * 192;
static constexpr size_t OFF_HEROH   = OFF_BOARDIN + SZ_BOARDIN;            // 12288*512
static constexpr size_t SZ_HEROH    = (size_t)MAXM * 6 * 512;
static constexpr size_t OFF_BOARDH  = OFF_HEROH + SZ_HEROH;                // 20480*512
static constexpr size_t SZ_BOARDH   = (size_t)MAXM * 10 * 512;
static constexpr size_t OFF_X       = OFF_BOARDH + SZ_BOARDH;              // 2048*2048
static constexpr size_t SZ_X        = (size_t)MAXM * 2048;
static constexpr size_t OFF_WFOLD   = OFF_X + SZ_X;                        // 2048*512
static constexpr size_t SZ_WFOLD    = (size_t)2048 * 512;
static constexpr size_t OFF_O1      = OFF_WFOLD + SZ_WFOLD;                // 2048*512
static constexpr size_t SZ_O1       = (size_t)MAXM * 512;
static constexpr size_t OFF_O2      = OFF_O1 + SZ_O1;                      // 2048*256
static constexpr size_t SZ_O2       = (size_t)MAXM * 256;
static constexpr size_t OFF_O3      = OFF_O2 + SZ_O2;                      // 2048*127
static constexpr size_t SZ_O3       = (size_t)MAXM * 127;
static constexpr size_t SCRATCH_TOTAL = OFF_O3 + SZ_O3;

__device__ float g_scratch[SCRATCH_TOTAL];

__constant__ int HP[6][2]  = {{0,1},{0,2},{0,3},{1,2},{1,3},{2,3}};
__constant__ int BT[10][3] = {{0,1,2},{0,1,3},{0,1,4},{0,2,3},{0,2,4},
                              {0,3,4},{1,2,3},{1,2,4},{1,3,4},{2,3,4}};

// ----------------------------------------------------------------------------
// prep: per-row card parse, double-stable-sort semantics == sort by (rank,suit),
// card id = (rank-1)*suit, gather embeddings into MLP input buffers.
// ----------------------------------------------------------------------------
__global__ void prep_kernel(const int* __restrict__ x, const float* __restrict__ emb,
                            float* __restrict__ heroIn, float* __restrict__ boardIn)
{
    int m = blockIdx.x;
    int t = threadIdx.x;  // 64 threads
    __shared__ int   cid[9];
    __shared__ float e9[9][EMBD];

    if (t == 0) {
        int key[9], c[9];
        #pragma unroll
        for (int i = 0; i < 9; i++) {
            int rk = x[m * 18 + 2 * i];
            int st = x[m * 18 + 2 * i + 1];
            key[i] = rk * 8 + st;          // primary rank, secondary suit
            c[i]   = (rk - 1) * st;        // card id in [0,48]
        }
        // insertion sort hero [0,4)
        for (int i = 1; i < 4; i++) {
            int k = key[i], v = c[i], j = i - 1;
            while (j >= 0 && key[j] > k) { key[j+1] = key[j]; c[j+1] = c[j]; j--; }
            key[j+1] = k; c[j+1] = v;
        }
        // insertion sort board [4,9)
        for (int i = 5; i < 9; i++) {
            int k = key[i], v = c[i], j = i - 1;
            while (j >= 4 && key[j] > k) { key[j+1] = key[j]; c[j+1] = c[j]; j--; }
            key[j+1] = k; c[j+1] = v;
        }
        #pragma unroll
        for (int i = 0; i < 9; i++) cid[i] = c[i];
    }
    __syncthreads();

    #pragma unroll
    for (int i = 0; i < 9; i++) e9[i][t] = emb[cid[i] * EMBD + t];
    // each thread reads only its own column t below -> no extra sync needed

    #pragma unroll
    for (int h = 0; h < 6; h++) {
        float* dst = heroIn + ((size_t)m * 6 + h) * 128;
        dst[t]      = e9[HP[h][0]][t];
        dst[64 + t] = e9[HP[h][1]][t];
    }
    #pragma unroll
    for (int b = 0; b < 10; b++) {
        float* dst = boardIn + ((size_t)m * 10 + b) * 192;
        dst[t]       = e9[4 + BT[b][0]][t];
        dst[64 + t]  = e9[4 + BT[b][1]][t];
        dst[128 + t] = e9[4 + BT[b][2]][t];
    }
}

// ----------------------------------------------------------------------------
// fold: Wfold[r][n], r<768: hero group h=r/128,k=r%128 -> sum over b of
// oW1[(256*(10h+b)+k)*512+n]; r>=768: board group, +128 row offset, sum over h.
// ----------------------------------------------------------------------------
__global__ void fold_kernel(const float* __restrict__ oW1, float* __restrict__ Wfold)
{
    int idx = blockIdx.x * blockDim.x + threadIdx.x;   // < 2048*512
    int r = idx >> 9;
    int n = idx & 511;
    float s = 0.f;
    if (r < 768) {
        int h = r >> 7, k = r & 127;
        #pragma unroll
        for (int b = 0; b < 10; b++)
            s += oW1[((size_t)((h * 10 + b) * 256 + k)) * 512 + n];
    } else {
        int rb = r - 768;
        int b = rb >> 7, k = rb & 127;
        #pragma unroll
        for (int h = 0; h < 6; h++)
            s += oW1[((size_t)((h * 10 + b) * 256 + 128 + k)) * 512 + n];
    }
    Wfold[idx] = s;
}

// ----------------------------------------------------------------------------
// Generic fp32 tiled GEMM: C = act(A[Mr x K] @ B[K x N] + bias)
// BM=64, BN=128, BK=16, 256 threads, 4x8 microtile. K must be a multiple of 16.
// Output addressing: divv==0 -> C[r*N+n]; else C[(r/divv)*ldOut + seg + (r%divv)*128 + n]
// ----------------------------------------------------------------------------
#define GBM 64
#define GBN 128
#define GBK 16

__global__ __launch_bounds__(256) void gemm_kernel(
    const float* __restrict__ A, const float* __restrict__ B,
    const float* __restrict__ bias, float* __restrict__ C,
    int Mr, int N, int K, int doRelu, int divv, int ldOut, int seg)
{
    __shared__ float As[GBK][GBM + 8];   // stride 72 floats = 288B (16B aligned)
    __shared__ float Bs[GBK][GBN];

    int tid = threadIdx.x;
    int m0 = blockIdx.y * GBM;
    int n0 = blockIdx.x * GBN;
    int tx = tid & 15;    // n dim (0..15) -> 8 cols each
    int ty = tid >> 4;    // m dim (0..15) -> 4 rows each

    float acc[4][8];
    #pragma unroll
    for (int i = 0; i < 4; i++)
        #pragma unroll
        for (int j = 0; j < 8; j++) acc[i][j] = 0.f;

    int ar = tid >> 2;              // 0..63
    int ac = (tid & 3) * 4;         // 0,4,8,12
    int brow = tid >> 5;            // 0..7
    int bcol = (tid & 31) * 4;      // 0..124
    bool nvec = ((N & 3) == 0);

    for (int k0 = 0; k0 < K; k0 += GBK) {
        // --- A tile (64x16), store transposed ---
        float4 av = make_float4(0.f, 0.f, 0.f, 0.f);
        int arow = m0 + ar;
        if (arow < Mr)
            av = *reinterpret_cast<const float4*>(A + (size_t)arow * K + k0 + ac);
        As[ac + 0][ar] = av.x;
        As[ac + 1][ar] = av.y;
        As[ac + 2][ar] = av.z;
        As[ac + 3][ar] = av.w;
        // --- B tile (16x128) ---
        #pragma unroll
        for (int i = 0; i < 2; i++) {
            int kr = k0 + brow + i * 8;
            int nc = n0 + bcol;
            float4 bv = make_float4(0.f, 0.f, 0.f, 0.f);
            if (nvec) {
                if (nc + 3 < N)
                    bv = *reinterpret_cast<const float4*>(B + (size_t)kr * N + nc);
            } else {
                const float* bp = B + (size_t)kr * N;
                if (nc + 0 < N) bv.x = bp[nc + 0];
                if (nc + 1 < N) bv.y = bp[nc + 1];
                if (nc + 2 < N) bv.z = bp[nc + 2];
                if (nc + 3 < N) bv.w = bp[nc + 3];
            }
            *reinterpret_cast<float4*>(&Bs[brow + i * 8][bcol]) = bv;
        }
        __syncthreads();

        #pragma unroll
        for (int kk = 0; kk < GBK; kk++) {
            float4 a  = *reinterpret_cast<const float4*>(&As[kk][ty * 4]);
            float4 b0 = *reinterpret_cast<const float4*>(&Bs[kk][tx * 8]);
            float4 b1 = *reinterpret_cast<const float4*>(&Bs[kk][tx * 8 + 4]);
            float av4[4] = {a.x, a.y, a.z, a.w};
            float bv8[8] = {b0.x, b0.y, b0.z, b0.w, b1.x, b1.y, b1.z, b1.w};
            #pragma unroll
            for (int i = 0; i < 4; i++)
                #pragma unroll
                for (int j = 0; j < 8; j++)
                    acc[i][j] += av4[i] * bv8[j];
        }
        __syncthreads();
    }

    #pragma unroll
    for (int i = 0; i < 4; i++) {
        int r = m0 + ty * 4 + i;
        if (r >= Mr) continue;
        size_t rowBase;
        if (divv == 0) rowBase = (size_t)r * N;
        else rowBase = (size_t)(r / divv) * ldOut + seg + (size_t)(r % divv) * 128;
        #pragma unroll
        for (int j = 0; j < 8; j++) {
            int n = n0 + tx * 8 + j;
            if (n >= N) continue;
            float v = acc[i][j] + bias[n];
            if (doRelu) v = (v > 0.f) ? v : 0.01f * v;
            C[rowBase + n] = v;
        }
    }
}

// ----------------------------------------------------------------------------
// final scorer: out[m][0..8] = O3[m] (127) @ sW (127x9) + sb
// ----------------------------------------------------------------------------
__global__ void final_kernel(const float* __restrict__ O3, const float* __restrict__ sW,
                             const float* __restrict__ sb, float* __restrict__ out)
{
    int m = blockIdx.x;
    __shared__ float row[127];
    for (int k = threadIdx.x; k < 127; k += 32) row[k] = O3[(size_t)m * 127 + k];
    __syncwarp();
    if (threadIdx.x < 9) {
        int n = threadIdx.x;
        float acc = sb[n];
        #pragma unroll 1
        for (int k = 0; k < 127; k++) acc += row[k] * sW[k * 9 + n];
        out[(size_t)m * 9 + n] = acc;
    }
}

// ----------------------------------------------------------------------------
extern "C" void kernel_launch(void* const* d_in, const int* in_sizes, int n_in,
                              void* d_out, int out_size)
{
    const int*   x   = (const int*)  d_in[0];
    const float* emb = (const float*)d_in[1];
    const float* hW1 = (const float*)d_in[2];
    const float* hb1 = (const float*)d_in[3];
    const float* hW2 = (const float*)d_in[4];
    const float* hb2 = (const float*)d_in[5];
    const float* bW1 = (const float*)d_in[6];
    const float* bb1 = (const float*)d_in[7];
    const float* bW2 = (const float*)d_in[8];
    const float* bb2 = (const float*)d_in[9];
    const float* oW1 = (const float*)d_in[10];
    const float* ob1 = (const float*)d_in[11];
    const float* oW2 = (const float*)d_in[12];
    const float* ob2 = (const float*)d_in[13];
    const float* oW3 = (const float*)d_in[14];
    const float* ob3 = (const float*)d_in[15];
    const float* sW  = (const float*)d_in[16];
    const float* sb  = (const float*)d_in[17];
    float* out = (float*)d_out;

    int M = in_sizes[0] / 18;
    if (M > MAXM) M = MAXM;

    float* base = nullptr;
    cudaGetSymbolAddress((void**)&base, g_scratch);
    float* heroIn  = base + OFF_HEROIN;
    float* boardIn = base + OFF_BOARDIN;
    float* heroH   = base + OFF_HEROH;
    float* boardH  = base + OFF_BOARDH;
    float* X       = base + OFF_X;
    float* Wfold   = base + OFF_WFOLD;
    float* O1      = base + OFF_O1;
    float* O2      = base + OFF_O2;
    float* O3      = base + OFF_O3;

    prep_kernel<<<M, 64>>>(x, emb, heroIn, boardIn);
    fold_kernel<<<(2048 * 512) / 256, 256>>>(oW1, Wfold);

    auto launch_gemm = [](const float* A, const float* B, const float* bias, float* C,
                          int Mr, int N, int K, int relu, int divv, int ldOut, int seg) {
        dim3 grid((N + GBN - 1) / GBN, (Mr + GBM - 1) / GBM);
        gemm_kernel<<<grid, 256>>>(A, B, bias, C, Mr, N, K, relu, divv, ldOut, seg);
    };

    // hero MLP: 128 -> 512 -> 128, second layer scattered into X[m][h*128 + n]
    launch_gemm(heroIn, hW1, hb1, heroH,  6 * M, 512, 128, 1, 0, 0, 0);
    launch_gemm(heroH,  hW2, hb2, X,      6 * M, 128, 512, 1, 6, 2048, 0);
    // board MLP: 192 -> 512 -> 128, into X[m][768 + b*128 + n]
    launch_gemm(boardIn, bW1, bb1, boardH, 10 * M, 512, 192, 1, 0, 0, 0);
    launch_gemm(boardH,  bW2, bb2, X,      10 * M, 128, 512, 1, 10, 2048, 768);
    // o-layers
    launch_gemm(X,  Wfold, ob1, O1, M, 512, 2048, 1, 0, 0, 0);
    launch_gemm(O1, oW2,   ob2, O2, M, 256,  512, 1, 0, 0, 0);
    launch_gemm(O2, oW3,   ob3, O3, M, 127,  256, 1, 0, 0, 0);
    // scorer
    final_kernel<<<M, 32>>>(O3, sW, sb, out);
    (void)out_size; (void)n_in;
}

// round 3
// speedup vs baseline: 2.9587x; 2.9587x over previous
#include <cuda_runtime.h>
#include <cuda_bf16.h>
#include <cstddef>
#include <cstdint>

// ============================================================================
// SmalldeckClassificationFlat — HMMA (mma.sync bf16) split-precision pipeline.
// Baseline PTX only (no tcgen05/TMA): cp.async + ldmatrix + mma.m16n8k16.
//   prep  : parse+sort cards -> heroIn/boardIn as bf16 hi/lo
//   fold  : Wfold[2048][512] fp32 = grouped sums of oW1 slices
//   wsplit: weights -> transposed [N][K] bf16 hi/lo
//   7 GEMMs, 3-term split (AhBh + AhBl + AlBh), fp32 accum.
//   Every epilogue re-emits bf16 hi/lo for the next layer.
// ============================================================================

#define EMBD 64
static constexpr int MAXM = 2048;

// --------------------- activation scratch (bf16 hi/lo) ----------------------
static constexpr size_t A_HEROIN  = 0;
static constexpr size_t S_HEROIN  = (size_t)MAXM * 6 * 128;
static constexpr size_t A_BOARDIN = A_HEROIN + S_HEROIN;
static constexpr size_t S_BOARDIN = (size_t)MAXM * 10 * 192;
static constexpr size_t A_HEROH   = A_BOARDIN + S_BOARDIN;
static constexpr size_t S_HEROH   = (size_t)MAXM * 6 * 512;
static constexpr size_t A_BOARDH  = A_HEROH + S_HEROH;
static constexpr size_t S_BOARDH  = (size_t)MAXM * 10 * 512;
static constexpr size_t A_X       = A_BOARDH + S_BOARDH;
static constexpr size_t S_X       = (size_t)MAXM * 2048;
static constexpr size_t A_O1      = A_X + S_X;
static constexpr size_t S_O1      = (size_t)MAXM * 512;
static constexpr size_t A_O2      = A_O1 + S_O1;
static constexpr size_t S_O2      = (size_t)MAXM * 256;
static constexpr size_t A_O3      = A_O2 + S_O2;
static constexpr size_t S_O3      = (size_t)MAXM * 128;
static constexpr size_t A_TOT     = A_O3 + S_O3;
__device__ __align__(256) __nv_bfloat16 g_ah[A_TOT];
__device__ __align__(256) __nv_bfloat16 g_al[A_TOT];

// --------------------------- weight scratch ---------------------------------
static constexpr size_t W_HW1 = 0;                       // 512x128
static constexpr size_t W_HW2 = W_HW1 + 512 * 128;       // 128x512
static constexpr size_t W_BW1 = W_HW2 + 128 * 512;       // 512x192
static constexpr size_t W_BW2 = W_BW1 + 512 * 192;       // 128x512
static constexpr size_t W_WF  = W_BW2 + 128 * 512;       // 512x2048
static constexpr size_t W_OW2 = W_WF  + 512 * 2048;      // 256x512
static constexpr size_t W_OW3 = W_OW2 + 256 * 512;       // 128x256 (row 127 zero)
static constexpr size_t W_TOT = W_OW3 + 128 * 256;
__device__ __align__(256) __nv_bfloat16 g_wh[W_TOT];
__device__ __align__(256) __nv_bfloat16 g_wl[W_TOT];

// fp32 scratch: Wfold only
__device__ __align__(256) float g_wfold[2048 * 512];

__constant__ int HP[6][2]  = {{0,1},{0,2},{0,3},{1,2},{1,3},{2,3}};
__constant__ int BT[10][3] = {{0,1,2},{0,1,3},{0,1,4},{0,2,3},{0,2,4},
                              {0,3,4},{1,2,3},{1,2,4},{1,3,4},{2,3,4}};

// ------------------------------ PTX helpers ---------------------------------
__device__ __forceinline__ uint32_t smem_to_u32(const void* p) {
    uint32_t a;
    asm("{ .reg .u64 t; cvta.to.shared.u64 t, %1; cvt.u32.u64 %0, t; }" : "=r"(a) : "l"(p));
    return a;
}
__device__ __forceinline__ void cp_async16(uint32_t dst, const void* src) {
    asm volatile("cp.async.cg.shared.global [%0], [%1], 16;\n" :: "r"(dst), "l"(src));
}
__device__ __forceinline__ void cp_commit() {
    asm volatile("cp.async.commit_group;\n" ::: "memory");
}
template <int N>
__device__ __forceinline__ void cp_wait() {
    asm volatile("cp.async.wait_group %0;\n" :: "n"(N) : "memory");
}
__device__ __forceinline__ void ldmA(uint32_t (&r)[4], uint32_t a) {
    asm volatile("ldmatrix.sync.aligned.m8n8.x4.shared.b16 {%0,%1,%2,%3}, [%4];"
                 : "=r"(r[0]), "=r"(r[1]), "=r"(r[2]), "=r"(r[3]) : "r"(a));
}
__device__ __forceinline__ void ldmB(uint32_t (&r)[2], uint32_t a) {
    asm volatile("ldmatrix.sync.aligned.m8n8.x2.shared.b16 {%0,%1}, [%2];"
                 : "=r"(r[0]), "=r"(r[1]) : "r"(a));
}
__device__ __forceinline__ void mma16816(float (&d)[4], const uint32_t (&a)[4],
                                         const uint32_t (&b)[2]) {
    asm volatile(
        "mma.sync.aligned.m16n8k16.row.col.f32.bf16.bf16.f32 "
        "{%0,%1,%2,%3}, {%4,%5,%6,%7}, {%8,%9}, {%0,%1,%2,%3};"
        : "+f"(d[0]), "+f"(d[1]), "+f"(d[2]), "+f"(d[3])
        : "r"(a[0]), "r"(a[1]), "r"(a[2]), "r"(a[3]), "r"(b[0]), "r"(b[1]));
}
__device__ __forceinline__ void split2(float v, __nv_bfloat16& h, __nv_bfloat16& l) {
    h = __float2bfloat16(v);
    l = __float2bfloat16(v - __bfloat162float(h));
}

// ----------------------------------------------------------------------------
// prep: sort cards, gather embeddings, emit bf16 hi/lo inputs
// ----------------------------------------------------------------------------
__global__ void prep_kernel(const int* __restrict__ x, const float* __restrict__ emb,
                            __nv_bfloat16* __restrict__ ah, __nv_bfloat16* __restrict__ al)
{
    int m = blockIdx.x;
    int t = threadIdx.x;  // 64
    __shared__ int   cid[9];
    __shared__ float e9[9][EMBD];

    if (t == 0) {
        int key[9], c[9];
        #pragma unroll
        for (int i = 0; i < 9; i++) {
            int rk = x[m * 18 + 2 * i];
            int st = x[m * 18 + 2 * i + 1];
            key[i] = rk * 8 + st;
            c[i]   = (rk - 1) * st;
        }
        for (int i = 1; i < 4; i++) {
            int k = key[i], v = c[i], j = i - 1;
            while (j >= 0 && key[j] > k) { key[j+1] = key[j]; c[j+1] = c[j]; j--; }
            key[j+1] = k; c[j+1] = v;
        }
        for (int i = 5; i < 9; i++) {
            int k = key[i], v = c[i], j = i - 1;
            while (j >= 4 && key[j] > k) { key[j+1] = key[j]; c[j+1] = c[j]; j--; }
            key[j+1] = k; c[j+1] = v;
        }
        #pragma unroll
        for (int i = 0; i < 9; i++) cid[i] = c[i];
    }
    __syncthreads();

    #pragma unroll
    for (int i = 0; i < 9; i++) e9[i][t] = emb[cid[i] * EMBD + t];

    __nv_bfloat16 h, l;
    #pragma unroll
    for (int hh = 0; hh < 6; hh++) {
        size_t base = A_HEROIN + ((size_t)m * 6 + hh) * 128;
        split2(e9[HP[hh][0]][t], h, l); ah[base + t] = h;      al[base + t] = l;
        split2(e9[HP[hh][1]][t], h, l); ah[base + 64 + t] = h; al[base + 64 + t] = l;
    }
    #pragma unroll
    for (int b = 0; b < 10; b++) {
        size_t base = A_BOARDIN + ((size_t)m * 10 + b) * 192;
        split2(e9[4 + BT[b][0]][t], h, l); ah[base + t] = h;       al[base + t] = l;
        split2(e9[4 + BT[b][1]][t], h, l); ah[base + 64 + t] = h;  al[base + 64 + t] = l;
        split2(e9[4 + BT[b][2]][t], h, l); ah[base + 128 + t] = h; al[base + 128 + t] = l;
    }
}

// ----------------------------------------------------------------------------
// fold: Wfold[r][n] fp32 (r<768 hero groups, else board groups)
// ----------------------------------------------------------------------------
__global__ void fold_kernel(const float* __restrict__ oW1, float* __restrict__ Wfold)
{
    int idx = blockIdx.x * blockDim.x + threadIdx.x;
    int r = idx >> 9;
    int n = idx & 511;
    float s = 0.f;
    if (r < 768) {
        int h = r >> 7, k = r & 127;
        #pragma unroll
        for (int b = 0; b < 10; b++)
            s += oW1[((size_t)((h * 10 + b) * 256 + k)) * 512 + n];
    } else {
        int rb = r - 768;
        int b = rb >> 7, k = rb & 127;
        #pragma unroll
        for (int h = 0; h < 6; h++)
            s += oW1[((size_t)((h * 10 + b) * 256 + 128 + k)) * 512 + n];
    }
    Wfold[idx] = s;
}

// ----------------------------------------------------------------------------
// wsplit: W[K][N] fp32 -> [Npad][K] bf16 hi/lo (rows >= N zeroed)
// ----------------------------------------------------------------------------
struct TD { const float* src; __nv_bfloat16* dh; __nv_bfloat16* dl; int K, N, Npad; };
struct TDArr { TD d[7]; };

__global__ void wsplit_kernel(TDArr descs)
{
    TD d = descs.d[blockIdx.z];
    int kt = blockIdx.x * 32, nt = blockIdx.y * 32;
    if (kt >= d.K || nt >= d.Npad) return;
    __shared__ float tile[32][33];
    for (int i = threadIdx.y; i < 32; i += 8) {
        int k = kt + i, n = nt + threadIdx.x;
        float v = (k < d.K && n < d.N) ? d.src[(size_t)k * d.N + n] : 0.f;
        tile[i][threadIdx.x] = v;
    }
    __syncthreads();
    for (int i = threadIdx.y; i < 32; i += 8) {
        int n = nt + i, k = kt + threadIdx.x;
        if (n < d.Npad && k < d.K) {
            float v = tile[threadIdx.x][i];
            __nv_bfloat16 h, l;
            split2(v, h, l);
            d.dh[(size_t)n * d.K + k] = h;
            d.dl[(size_t)n * d.K + k] = l;
        }
    }
}

// ----------------------------------------------------------------------------
// HMMA GEMM: C = lrelu(A @ B^T + bias), 3-term bf16 split, fp32 accum.
// A: [Mr][K] bf16 hi/lo, B: [Npad][K] bf16 hi/lo (col-major k x n for mma).
// BN=128, BK=32, 8 warps, warp tile (BM/2)x32, double-buffered cp.async.
// Epilogue emits bf16 hi/lo (Ch/Cl) with optional scatter:
//   divv==0 -> row r at r*ldOut ; else (r/divv)*ldOut + seg + (r%divv)*128
// Mr % BM == 0, N % 128 == 0, K % 32 == 0 (guaranteed by caller).
// ----------------------------------------------------------------------------
template<int BM>
__global__ void __launch_bounds__(256, 2) hmma_gemm(
    const __nv_bfloat16* __restrict__ Ah, const __nv_bfloat16* __restrict__ Al,
    const __nv_bfloat16* __restrict__ Bh, const __nv_bfloat16* __restrict__ Bl,
    const float* __restrict__ bias, int nbias,
    __nv_bfloat16* __restrict__ Ch, __nv_bfloat16* __restrict__ Cl,
    int K, int divv, int ldOut, int seg)
{
    constexpr int ROWB = 80;              // 32 bf16 + 16B pad
    constexpr int SA = BM * ROWB;
    constexpr int SB = 128 * ROWB;
    constexpr int STG = 2 * SA + 2 * SB;
    constexpr int MF = BM / 32;           // 16-row frags per warp

    extern __shared__ char smem[];
    uint32_t sbase = smem_to_u32(smem);

    int tid = threadIdx.x, lane = tid & 31, wid = tid >> 5;
    int wy = wid & 1, wx = wid >> 1;
    int m0 = blockIdx.y * BM, n0 = blockIdx.x * 128;

    float acc[MF][4][4];
    #pragma unroll
    for (int i = 0; i < MF; i++)
        #pragma unroll
        for (int j = 0; j < 4; j++)
            #pragma unroll
            for (int q = 0; q < 4; q++) acc[i][j][q] = 0.f;

    auto load_stage = [&](int k0, int st) {
        uint32_t s0 = sbase + st * STG;
        #pragma unroll
        for (int i = tid; i < BM * 4; i += 256) {
            int row = i >> 2, c = i & 3;
            size_t go = (size_t)(m0 + row) * K + k0 + c * 8;
            cp_async16(s0 + row * ROWB + c * 16, Ah + go);
            cp_async16(s0 + SA + row * ROWB + c * 16, Al + go);
        }
        #pragma unroll
        for (int i = tid; i < 512; i += 256) {
            int row = i >> 2, c = i & 3;
            size_t go = (size_t)(n0 + row) * K + k0 + c * 8;
            cp_async16(s0 + 2 * SA + row * ROWB + c * 16, Bh + go);
            cp_async16(s0 + 2 * SA + SB + row * ROWB + c * 16, Bl + go);
        }
    };

    uint32_t a_off = (uint32_t)((wy * (BM / 2) + (lane & 15)) * ROWB + (lane >> 4) * 16);
    uint32_t b_off = (uint32_t)(2 * SA + (wx * 32 + (lane & 7)) * ROWB + ((lane >> 3) & 1) * 16);

    int nch = K >> 5;
    load_stage(0, 0);
    cp_commit();

    for (int ch = 0; ch < nch; ch++) {
        if (ch + 1 < nch) {
            load_stage((ch + 1) << 5, (ch + 1) & 1);
            cp_commit();
            cp_wait<1>();
        } else {
            cp_wait<0>();
        }
        __syncthreads();

        uint32_t s0 = sbase + (uint32_t)(ch & 1) * STG;
        #pragma unroll
        for (int k16 = 0; k16 < 2; k16++) {
            uint32_t bk = (uint32_t)k16 * 32;
            uint32_t bh[4][2], bl[4][2];
            #pragma unroll
            for (int ni = 0; ni < 4; ni++) {
                uint32_t ad = s0 + b_off + ni * (8 * ROWB) + bk;
                ldmB(bh[ni], ad);
                ldmB(bl[ni], ad + SB);
            }
            #pragma unroll
            for (int mi = 0; mi < MF; mi++) {
                uint32_t ah4[4], al4[4];
                uint32_t ad = s0 + a_off + mi * (16 * ROWB) + bk;
                ldmA(ah4, ad);
                ldmA(al4, ad + SA);
                #pragma unroll
                for (int ni = 0; ni < 4; ni++) {
                    mma16816(acc[mi][ni], ah4, bh[ni]);
                    mma16816(acc[mi][ni], ah4, bl[ni]);
                    mma16816(acc[mi][ni], al4, bh[ni]);
                }
            }
        }
        __syncthreads();
    }

    // ---- epilogue: bias + leaky-relu, emit bf16 hi/lo pairs ----
    #pragma unroll
    for (int mi = 0; mi < MF; mi++) {
        #pragma unroll
        for (int ni = 0; ni < 4; ni++) {
            int n = n0 + wx * 32 + ni * 8 + 2 * (lane & 3);
            float bv0 = (n < nbias) ? bias[n] : 0.f;
            float bv1 = (n + 1 < nbias) ? bias[n + 1] : 0.f;
            #pragma unroll
            for (int half = 0; half < 2; half++) {
                int r = m0 + wy * (BM / 2) + mi * 16 + (lane >> 2) + half * 8;
                float v0 = acc[mi][ni][half * 2 + 0] + bv0;
                float v1 = acc[mi][ni][half * 2 + 1] + bv1;
                v0 = (v0 > 0.f) ? v0 : 0.01f * v0;
                v1 = (v1 > 0.f) ? v1 : 0.01f * v1;
                size_t base;
                if (divv == 0) base = (size_t)r * ldOut + n;
                else base = (size_t)(r / divv) * ldOut + seg + (size_t)(r % divv) * 128 + n;
                __nv_bfloat16 h0, l0, h1, l1;
                split2(v0, h0, l0);
                split2(v1, h1, l1);
                uint32_t hp = (uint32_t)(*(uint16_t*)&h0) | ((uint32_t)(*(uint16_t*)&h1) << 16);
                uint32_t lp = (uint32_t)(*(uint16_t*)&l0) | ((uint32_t)(*(uint16_t*)&l1) << 16);
                *reinterpret_cast<uint32_t*>(Ch + base) = hp;
                *reinterpret_cast<uint32_t*>(Cl + base) = lp;
            }
        }
    }
}

// ----------------------------------------------------------------------------
// final scorer: out[m] = O3[m](127, hi+lo) @ sW + sb
// ----------------------------------------------------------------------------
__global__ void final_kernel(const __nv_bfloat16* __restrict__ O3h,
                             const __nv_bfloat16* __restrict__ O3l,
                             const float* __restrict__ sW,
                             const float* __restrict__ sb, float* __restrict__ out)
{
    int m = blockIdx.x;
    __shared__ float row[127];
    for (int k = threadIdx.x; k < 127; k += 32)
        row[k] = __bfloat162float(O3h[(size_t)m * 128 + k]) +
                 __bfloat162float(O3l[(size_t)m * 128 + k]);
    __syncwarp();
    if (threadIdx.x < 9) {
        int n = threadIdx.x;
        float acc = sb[n];
        #pragma unroll 1
        for (int k = 0; k < 127; k++) acc += row[k] * sW[k * 9 + n];
        out[(size_t)m * 9 + n] = acc;
    }
}

// ----------------------------------------------------------------------------
extern "C" void kernel_launch(void* const* d_in, const int* in_sizes, int n_in,
                              void* d_out, int out_size)
{
    const int*   x   = (const int*)  d_in[0];
    const float* emb = (const float*)d_in[1];
    const float* hW1 = (const float*)d_in[2];
    const float* hb1 = (const float*)d_in[3];
    const float* hW2 = (const float*)d_in[4];
    const float* hb2 = (const float*)d_in[5];
    const float* bW1 = (const float*)d_in[6];
    const float* bb1 = (const float*)d_in[7];
    const float* bW2 = (const float*)d_in[8];
    const float* bb2 = (const float*)d_in[9];
    const float* oW1 = (const float*)d_in[10];
    const float* ob1 = (const float*)d_in[11];
    const float* oW2 = (const float*)d_in[12];
    const float* ob2 = (const float*)d_in[13];
    const float* oW3 = (const float*)d_in[14];
    const float* ob3 = (const float*)d_in[15];
    const float* sW  = (const float*)d_in[16];
    const float* sb  = (const float*)d_in[17];
    float* out = (float*)d_out;

    int M = in_sizes[0] / 18;
    if (M > MAXM) M = MAXM;

    __nv_bfloat16 *ah = nullptr, *al = nullptr, *wh = nullptr, *wl = nullptr;
    float* wfold = nullptr;
    cudaGetSymbolAddress((void**)&ah, g_ah);
    cudaGetSymbolAddress((void**)&al, g_al);
    cudaGetSymbolAddress((void**)&wh, g_wh);
    cudaGetSymbolAddress((void**)&wl, g_wl);
    cudaGetSymbolAddress((void**)&wfold, g_wfold);

    constexpr int SMEM128 = 2 * (2 * 128 * 80 + 2 * 128 * 80);   // 81920
    constexpr int SMEM64  = 2 * (2 * 64 * 80 + 2 * 128 * 80);    // 61440
    cudaFuncSetAttribute(hmma_gemm<128>, cudaFuncAttributeMaxDynamicSharedMemorySize, SMEM128);
    cudaFuncSetAttribute(hmma_gemm<64>,  cudaFuncAttributeMaxDynamicSharedMemorySize, SMEM64);

    prep_kernel<<<M, 64>>>(x, emb, ah, al);
    fold_kernel<<<(2048 * 512) / 256, 256>>>(oW1, wfold);

    TDArr td;
    td.d[0] = { hW1,   wh + W_HW1, wl + W_HW1, 128,  512, 512 };
    td.d[1] = { hW2,   wh + W_HW2, wl + W_HW2, 512,  128, 128 };
    td.d[2] = { bW1,   wh + W_BW1, wl + W_BW1, 192,  512, 512 };
    td.d[3] = { bW2,   wh + W_BW2, wl + W_BW2, 512,  128, 128 };
    td.d[4] = { wfold, wh + W_WF,  wl + W_WF,  2048, 512, 512 };
    td.d[5] = { oW2,   wh + W_OW2, wl + W_OW2, 512,  256, 256 };
    td.d[6] = { oW3,   wh + W_OW3, wl + W_OW3, 256,  127, 128 };
    wsplit_kernel<<<dim3(64, 16, 7), dim3(32, 8)>>>(td);

    // GEMM launches ------------------------------------------------------
    // hero1: [6M x 512] = heroIn[6M x 128] @ hW1^T
    hmma_gemm<128><<<dim3(512 / 128, (6 * M) / 128), 256, SMEM128>>>(
        ah + A_HEROIN, al + A_HEROIN, wh + W_HW1, wl + W_HW1,
        hb1, 512, ah + A_HEROH, al + A_HEROH, 128, 0, 512, 0);
    // hero2: [6M x 128] -> scatter into X[m][h*128 + n]
    hmma_gemm<64><<<dim3(1, (6 * M) / 64), 256, SMEM64>>>(
        ah + A_HEROH, al + A_HEROH, wh + W_HW2, wl + W_HW2,
        hb2, 128, ah + A_X, al + A_X, 512, 6, 2048, 0);
    // board1: [10M x 512] = boardIn[10M x 192] @ bW1^T
    hmma_gemm<128><<<dim3(512 / 128, (10 * M) / 128), 256, SMEM128>>>(
        ah + A_BOARDIN, al + A_BOARDIN, wh + W_BW1, wl + W_BW1,
        bb1, 512, ah + A_BOARDH, al + A_BOARDH, 192, 0, 512, 0);
    // board2: [10M x 128] -> scatter into X[m][768 + b*128 + n]
    hmma_gemm<128><<<dim3(1, (10 * M) / 128), 256, SMEM128>>>(
        ah + A_BOARDH, al + A_BOARDH, wh + W_BW2, wl + W_BW2,
        bb2, 128, ah + A_X, al + A_X, 512, 10, 2048, 768);
    // o1: [M x 512] = X[M x 2048] @ Wfold^T
    hmma_gemm<64><<<dim3(512 / 128, M / 64), 256, SMEM64>>>(
        ah + A_X, al + A_X, wh + W_WF, wl + W_WF,
        ob1, 512, ah + A_O1, al + A_O1, 2048, 0, 512, 0);
    // o2: [M x 256]
    hmma_gemm<64><<<dim3(256 / 128, M / 64), 256, SMEM64>>>(
        ah + A_O1, al + A_O1, wh + W_OW2, wl + W_OW2,
        ob2, 256, ah + A_O2, al + A_O2, 512, 0, 256, 0);
    // o3: [M x 128(pad, 127 real)]
    hmma_gemm<64><<<dim3(1, M / 64), 256, SMEM64>>>(
        ah + A_O2, al + A_O2, wh + W_OW3, wl + W_OW3,
        ob3, 127, ah + A_O3, al + A_O3, 256, 0, 128, 0);

    final_kernel<<<M, 32>>>(ah + A_O3, al + A_O3, sW, sb, out);
    (void)out_size; (void)n_in;
}

// round 4
// speedup vs baseline: 4.2800x; 1.4466x over previous
#include <cuda_runtime.h>
#include <cuda_fp16.h>
#include <cstddef>
#include <cstdint>

// ============================================================================
// SmalldeckClassificationFlat — fp16 2-term split HMMA pipeline.
//   C = (Ah + Al) @ Bh^T : A split into fp16 hi/lo (exact to 2^-22),
//   B single fp16 (error ~2^-12 relative, well under 1e-3 budget).
//   cp.async 3-stage ring + ldmatrix + mma.m16n8k16.f32.f16.f16.f32.
//   Merged dual-segment launches for hero/board layer pairs.
// ============================================================================

#define EMBD 64
static constexpr int MAXM = 2048;

// --------------------- activation scratch (fp16 hi/lo) ----------------------
static constexpr size_t A_HEROIN  = 0;
static constexpr size_t S_HEROIN  = (size_t)MAXM * 6 * 128;
static constexpr size_t A_BOARDIN = A_HEROIN + S_HEROIN;
static constexpr size_t S_BOARDIN = (size_t)MAXM * 10 * 192;
static constexpr size_t A_HEROH   = A_BOARDIN + S_BOARDIN;
static constexpr size_t S_HEROH   = (size_t)MAXM * 6 * 512;
static constexpr size_t A_BOARDH  = A_HEROH + S_HEROH;
static constexpr size_t S_BOARDH  = (size_t)MAXM * 10 * 512;
static constexpr size_t A_X       = A_BOARDH + S_BOARDH;
static constexpr size_t S_X       = (size_t)MAXM * 2048;
static constexpr size_t A_O1      = A_X + S_X;
static constexpr size_t S_O1      = (size_t)MAXM * 512;
static constexpr size_t A_O2      = A_O1 + S_O1;
static constexpr size_t S_O2      = (size_t)MAXM * 256;
static constexpr size_t A_O3      = A_O2 + S_O2;
static constexpr size_t S_O3      = (size_t)MAXM * 128;
static constexpr size_t A_TOT     = A_O3 + S_O3;
__device__ __align__(256) __half g_ah[A_TOT];
__device__ __align__(256) __half g_al[A_TOT];

// --------------------------- weight scratch (fp16, single) ------------------
static constexpr size_t W_HW1 = 0;                       // 512x128
static constexpr size_t W_HW2 = W_HW1 + 512 * 128;       // 128x512
static constexpr size_t W_BW1 = W_HW2 + 128 * 512;       // 512x192
static constexpr size_t W_BW2 = W_BW1 + 512 * 192;       // 128x512
static constexpr size_t W_WF  = W_BW2 + 128 * 512;       // 512x2048 (fold, fused)
static constexpr size_t W_OW2 = W_WF  + 512 * 2048;      // 256x512
static constexpr size_t W_OW3 = W_OW2 + 256 * 512;       // 128x256 (row 127 zero)
static constexpr size_t W_TOT = W_OW3 + 128 * 256;
__device__ __align__(256) __half g_wh[W_TOT];

__constant__ int HP[6][2]  = {{0,1},{0,2},{0,3},{1,2},{1,3},{2,3}};
__constant__ int BT[10][3] = {{0,1,2},{0,1,3},{0,1,4},{0,2,3},{0,2,4},
                              {0,3,4},{1,2,3},{1,2,4},{1,3,4},{2,3,4}};

// ------------------------------ PTX helpers ---------------------------------
__device__ __forceinline__ uint32_t smem_to_u32(const void* p) {
    uint32_t a;
    asm("{ .reg .u64 t; cvta.to.shared.u64 t, %1; cvt.u32.u64 %0, t; }" : "=r"(a) : "l"(p));
    return a;
}
__device__ __forceinline__ void cp_async16(uint32_t dst, const void* src) {
    asm volatile("cp.async.cg.shared.global [%0], [%1], 16;\n" :: "r"(dst), "l"(src));
}
__device__ __forceinline__ void cp_commit() {
    asm volatile("cp.async.commit_group;\n" ::: "memory");
}
template <int N>
__device__ __forceinline__ void cp_wait() {
    asm volatile("cp.async.wait_group %0;\n" :: "n"(N) : "memory");
}
__device__ __forceinline__ void ldmA(uint32_t (&r)[4], uint32_t a) {
    asm volatile("ldmatrix.sync.aligned.m8n8.x4.shared.b16 {%0,%1,%2,%3}, [%4];"
                 : "=r"(r[0]), "=r"(r[1]), "=r"(r[2]), "=r"(r[3]) : "r"(a));
}
__device__ __forceinline__ void ldmB(uint32_t (&r)[2], uint32_t a) {
    asm volatile("ldmatrix.sync.aligned.m8n8.x2.shared.b16 {%0,%1}, [%2];"
                 : "=r"(r[0]), "=r"(r[1]) : "r"(a));
}
__device__ __forceinline__ void mma16816(float (&d)[4], const uint32_t (&a)[4],
                                         const uint32_t (&b)[2]) {
    asm volatile(
        "mma.sync.aligned.m16n8k16.row.col.f32.f16.f16.f32 "
        "{%0,%1,%2,%3}, {%4,%5,%6,%7}, {%8,%9}, {%0,%1,%2,%3};"
        : "+f"(d[0]), "+f"(d[1]), "+f"(d[2]), "+f"(d[3])
        : "r"(a[0]), "r"(a[1]), "r"(a[2]), "r"(a[3]), "r"(b[0]), "r"(b[1]));
}
__device__ __forceinline__ void split2h(float v, __half& h, __half& l) {
    h = __float2half_rn(v);
    l = __float2half_rn(v - __half2float(h));
}

// ----------------------------------------------------------------------------
// prep: sort cards, gather embeddings, emit fp16 hi/lo inputs
// ----------------------------------------------------------------------------
__global__ void prep_kernel(const int* __restrict__ x, const float* __restrict__ emb,
                            __half* __restrict__ ah, __half* __restrict__ al)
{
    int m = blockIdx.x;
    int t = threadIdx.x;  // 64
    __shared__ int   cid[9];
    __shared__ float e9[9][EMBD];

    if (t == 0) {
        int key[9], c[9];
        #pragma unroll
        for (int i = 0; i < 9; i++) {
            int rk = x[m * 18 + 2 * i];
            int st = x[m * 18 + 2 * i + 1];
            key[i] = rk * 8 + st;
            c[i]   = (rk - 1) * st;
        }
        for (int i = 1; i < 4; i++) {
            int k = key[i], v = c[i], j = i - 1;
            while (j >= 0 && key[j] > k) { key[j+1] = key[j]; c[j+1] = c[j]; j--; }
            key[j+1] = k; c[j+1] = v;
        }
        for (int i = 5; i < 9; i++) {
            int k = key[i], v = c[i], j = i - 1;
            while (j >= 4 && key[j] > k) { key[j+1] = key[j]; c[j+1] = c[j]; j--; }
            key[j+1] = k; c[j+1] = v;
        }
        #pragma unroll
        for (int i = 0; i < 9; i++) cid[i] = c[i];
    }
    __syncthreads();

    #pragma unroll
    for (int i = 0; i < 9; i++) e9[i][t] = emb[cid[i] * EMBD + t];

    __half h, l;
    #pragma unroll
    for (int hh = 0; hh < 6; hh++) {
        size_t base = A_HEROIN + ((size_t)m * 6 + hh) * 128;
        split2h(e9[HP[hh][0]][t], h, l); ah[base + t] = h;      al[base + t] = l;
        split2h(e9[HP[hh][1]][t], h, l); ah[base + 64 + t] = h; al[base + 64 + t] = l;
    }
    #pragma unroll
    for (int b = 0; b < 10; b++) {
        size_t base = A_BOARDIN + ((size_t)m * 10 + b) * 192;
        split2h(e9[4 + BT[b][0]][t], h, l); ah[base + t] = h;       al[base + t] = l;
        split2h(e9[4 + BT[b][1]][t], h, l); ah[base + 64 + t] = h;  al[base + 64 + t] = l;
        split2h(e9[4 + BT[b][2]][t], h, l); ah[base + 128 + t] = h; al[base + 128 + t] = l;
    }
}

// ----------------------------------------------------------------------------
// fold+split fused: Wfold[r][n] = grouped sums of oW1; write fp16 transposed
// into g_wh[W_WF + n*2048 + r].  Tiles 32(r) x 32(n), 32x8 threads.
// ----------------------------------------------------------------------------
__global__ void fold_split_kernel(const float* __restrict__ oW1, __half* __restrict__ dh)
{
    int r0 = blockIdx.x * 32, n0 = blockIdx.y * 32;
    int tx = threadIdx.x, ty = threadIdx.y;
    __shared__ float t[32][33];
    #pragma unroll
    for (int j = 0; j < 4; j++) {
        int r = r0 + ty + 8 * j;
        int n = n0 + tx;
        float s = 0.f;
        if (r < 768) {
            int h = r >> 7, k = r & 127;
            #pragma unroll
            for (int b = 0; b < 10; b++)
                s += oW1[((size_t)((h * 10 + b) * 256 + k)) * 512 + n];
        } else {
            int rb = r - 768;
            int b = rb >> 7, k = rb & 127;
            #pragma unroll
            for (int h = 0; h < 6; h++)
                s += oW1[((size_t)((h * 10 + b) * 256 + 128 + k)) * 512 + n];
        }
        t[ty + 8 * j][tx] = s;
    }
    __syncthreads();
    #pragma unroll
    for (int j = 0; j < 4; j++) {
        int nl = ty + 8 * j;
        dh[W_WF + (size_t)(n0 + nl) * 2048 + r0 + tx] = __float2half_rn(t[tx][nl]);
    }
}

// ----------------------------------------------------------------------------
// wsplit: W[K][N] fp32 -> [Npad][K] fp16 (rows >= N zeroed)
// ----------------------------------------------------------------------------
struct TD { const float* src; __half* dh; int K, N, Npad; };
struct TDArr { TD d[6]; };

__global__ void wsplit_kernel(TDArr descs)
{
    TD d = descs.d[blockIdx.z];
    int kt = blockIdx.x * 32, nt = blockIdx.y * 32;
    if (kt >= d.K || nt >= d.Npad) return;
    __shared__ float tile[32][33];
    for (int i = threadIdx.y; i < 32; i += 8) {
        int k = kt + i, n = nt + threadIdx.x;
        float v = (k < d.K && n < d.N) ? d.src[(size_t)k * d.N + n] : 0.f;
        tile[i][threadIdx.x] = v;
    }
    __syncthreads();
    for (int i = threadIdx.y; i < 32; i += 8) {
        int n = nt + i, k = kt + threadIdx.x;
        if (n < d.Npad && k < d.K)
            d.dh[(size_t)n * d.K + k] = __float2half_rn(tile[threadIdx.x][i]);
    }
}

// ----------------------------------------------------------------------------
// HMMA GEMM, 2-term fp16 split: C = lrelu((Ah+Al) @ Bh^T + bias).
// BN=128, BK=32, 8 warps, 3-stage cp.async ring, 1 syncthreads per chunk.
// Dual-segment: CTA picks param set by blockIdx.y (< p0.yb -> p0, else p1).
// Epilogue emits fp16 hi/lo (Ch/Cl) with optional scatter:
//   divv==0 -> row r at r*ldOut ; else (r/divv)*ldOut + seg + (r%divv)*128
// Mr % BM == 0, N % 128 == 0, K % 32 == 0.
// ----------------------------------------------------------------------------
struct GemmP {
    const __half* Ah; const __half* Al; const __half* Bh;
    const float* bias; int nbias;
    __half* Ch; __half* Cl;
    int K, divv, ldOut, seg, yb;
};

template<int BM>
__global__ void __launch_bounds__(256, 2) hmma_gemm(GemmP p0, GemmP p1)
{
    constexpr int ROWB = 80;              // 32 fp16 (64B) + 16B pad
    constexpr int SA = BM * ROWB;
    constexpr int SB = 128 * ROWB;
    constexpr int STG = 2 * SA + SB;
    constexpr int MF = BM / 32;

    bool first = (blockIdx.y < (unsigned)p0.yb);
    GemmP p = first ? p0 : p1;
    int my = first ? blockIdx.y : (blockIdx.y - p0.yb);

    extern __shared__ char smem[];
    uint32_t sbase = smem_to_u32(smem);

    int tid = threadIdx.x, lane = tid & 31, wid = tid >> 5;
    int wy = wid & 1, wx = wid >> 1;
    int m0 = my * BM, n0 = blockIdx.x * 128;
    int K = p.K;

    float acc[MF][4][4];
    #pragma unroll
    for (int i = 0; i < MF; i++)
        #pragma unroll
        for (int j = 0; j < 4; j++)
            #pragma unroll
            for (int q = 0; q < 4; q++) acc[i][j][q] = 0.f;

    auto load_stage = [&](int k0, int st) {
        uint32_t s0 = sbase + (uint32_t)st * STG;
        for (int i = tid; i < BM * 4; i += 256) {
            int row = i >> 2, c = i & 3;
            size_t go = (size_t)(m0 + row) * K + k0 + c * 8;
            cp_async16(s0 + row * ROWB + c * 16, p.Ah + go);
            cp_async16(s0 + SA + row * ROWB + c * 16, p.Al + go);
        }
        for (int i = tid; i < 512; i += 256) {
            int row = i >> 2, c = i & 3;
            size_t go = (size_t)(n0 + row) * K + k0 + c * 8;
            cp_async16(s0 + 2 * SA + row * ROWB + c * 16, p.Bh + go);
        }
    };

    uint32_t a_off = (uint32_t)((wy * (BM / 2) + (lane & 15)) * ROWB + (lane >> 4) * 16);
    uint32_t b_off = (uint32_t)(2 * SA + (wx * 32 + (lane & 7)) * ROWB + ((lane >> 3) & 1) * 16);

    int nch = K >> 5;
    load_stage(0, 0);
    cp_commit();
    if (nch > 1) load_stage(32, 1);
    cp_commit();

    for (int ch = 0; ch < nch; ch++) {
        cp_wait<1>();
        __syncthreads();
        if (ch + 2 < nch) load_stage((ch + 2) << 5, (ch + 2) % 3);
        cp_commit();

        uint32_t s0 = sbase + (uint32_t)(ch % 3) * STG;
        #pragma unroll
        for (int k16 = 0; k16 < 2; k16++) {
            uint32_t bk = (uint32_t)k16 * 32;
            uint32_t bh[4][2];
            #pragma unroll
            for (int ni = 0; ni < 4; ni++)
                ldmB(bh[ni], s0 + b_off + ni * (8 * ROWB) + bk);
            #pragma unroll
            for (int mi = 0; mi < MF; mi++) {
                uint32_t ah4[4], al4[4];
                uint32_t ad = s0 + a_off + mi * (16 * ROWB) + bk;
                ldmA(ah4, ad);
                ldmA(al4, ad + SA);
                #pragma unroll
                for (int ni = 0; ni < 4; ni++) {
                    mma16816(acc[mi][ni], ah4, bh[ni]);
                    mma16816(acc[mi][ni], al4, bh[ni]);
                }
            }
        }
    }

    // ---- epilogue: bias + leaky-relu, emit fp16 hi/lo pairs ----
    #pragma unroll
    for (int mi = 0; mi < MF; mi++) {
        #pragma unroll
        for (int ni = 0; ni < 4; ni++) {
            int n = n0 + wx * 32 + ni * 8 + 2 * (lane & 3);
            float bv0 = (n < p.nbias) ? p.bias[n] : 0.f;
            float bv1 = (n + 1 < p.nbias) ? p.bias[n + 1] : 0.f;
            #pragma unroll
            for (int half = 0; half < 2; half++) {
                int r = m0 + wy * (BM / 2) + mi * 16 + (lane >> 2) + half * 8;
                float v0 = acc[mi][ni][half * 2 + 0] + bv0;
                float v1 = acc[mi][ni][half * 2 + 1] + bv1;
                v0 = (v0 > 0.f) ? v0 : 0.01f * v0;
                v1 = (v1 > 0.f) ? v1 : 0.01f * v1;
                size_t base;
                if (p.divv == 0) base = (size_t)r * p.ldOut + n;
                else base = (size_t)(r / p.divv) * p.ldOut + p.seg
                          + (size_t)(r % p.divv) * 128 + n;
                __half h0, l0, h1, l1;
                split2h(v0, h0, l0);
                split2h(v1, h1, l1);
                uint32_t hp = (uint32_t)(*(uint16_t*)&h0) | ((uint32_t)(*(uint16_t*)&h1) << 16);
                uint32_t lp = (uint32_t)(*(uint16_t*)&l0) | ((uint32_t)(*(uint16_t*)&l1) << 16);
                *reinterpret_cast<uint32_t*>(p.Ch + base) = hp;
                *reinterpret_cast<uint32_t*>(p.Cl + base) = lp;
            }
        }
    }
}

// ----------------------------------------------------------------------------
// final scorer: out[m] = O3[m](127, hi+lo) @ sW + sb
// ----------------------------------------------------------------------------
__global__ void final_kernel(const __half* __restrict__ O3h,
                             const __half* __restrict__ O3l,
                             const float* __restrict__ sW,
                             const float* __restrict__ sb, float* __restrict__ out)
{
    int m = blockIdx.x;
    __shared__ float row[127];
    for (int k = threadIdx.x; k < 127; k += 32)
        row[k] = __half2float(O3h[(size_t)m * 128 + k]) +
                 __half2float(O3l[(size_t)m * 128 + k]);
    __syncwarp();
    if (threadIdx.x < 9) {
        int n = threadIdx.x;
        float acc = sb[n];
        #pragma unroll 1
        for (int k = 0; k < 127; k++) acc += row[k] * sW[k * 9 + n];
        out[(size_t)m * 9 + n] = acc;
    }
}

// ----------------------------------------------------------------------------
extern "C" void kernel_launch(void* const* d_in, const int* in_sizes, int n_in,
                              void* d_out, int out_size)
{
    const int*   x   = (const int*)  d_in[0];
    const float* emb = (const float*)d_in[1];
    const float* hW1 = (const float*)d_in[2];
    const float* hb1 = (const float*)d_in[3];
    const float* hW2 = (const float*)d_in[4];
    const float* hb2 = (const float*)d_in[5];
    const float* bW1 = (const float*)d_in[6];
    const float* bb1 = (const float*)d_in[7];
    const float* bW2 = (const float*)d_in[8];
    const float* bb2 = (const float*)d_in[9];
    const float* oW1 = (const float*)d_in[10];
    const float* ob1 = (const float*)d_in[11];
    const float* oW2 = (const float*)d_in[12];
    const float* ob2 = (const float*)d_in[13];
    const float* oW3 = (const float*)d_in[14];
    const float* ob3 = (const float*)d_in[15];
    const float* sW  = (const float*)d_in[16];
    const float* sb  = (const float*)d_in[17];
    float* out = (float*)d_out;

    int M = in_sizes[0] / 18;
    if (M > MAXM) M = MAXM;

    __half *ah = nullptr, *al = nullptr, *wh = nullptr;
    cudaGetSymbolAddress((void**)&ah, g_ah);
    cudaGetSymbolAddress((void**)&al, g_al);
    cudaGetSymbolAddress((void**)&wh, g_wh);

    constexpr int SMEM128 = 3 * (2 * 128 * 80 + 128 * 80);   // 92160
    constexpr int SMEM32  = 3 * (2 * 32 * 80 + 128 * 80);    // 46080
    cudaFuncSetAttribute(hmma_gemm<128>, cudaFuncAttributeMaxDynamicSharedMemorySize, SMEM128);
    cudaFuncSetAttribute(hmma_gemm<32>,  cudaFuncAttributeMaxDynamicSharedMemorySize, SMEM32);

    prep_kernel<<<M, 64>>>(x, emb, ah, al);
    fold_split_kernel<<<dim3(64, 16), dim3(32, 8)>>>(oW1, wh);

    TDArr td;
    td.d[0] = { hW1, wh + W_HW1, 128, 512, 512 };
    td.d[1] = { hW2, wh + W_HW2, 512, 128, 128 };
    td.d[2] = { bW1, wh + W_BW1, 192, 512, 512 };
    td.d[3] = { bW2, wh + W_BW2, 512, 128, 128 };
    td.d[4] = { oW2, wh + W_OW2, 512, 256, 256 };
    td.d[5] = { oW3, wh + W_OW3, 256, 127, 128 };
    wsplit_kernel<<<dim3(64, 16, 6), dim3(32, 8)>>>(td);

    int yh1 = (6 * M) / 128, yb1 = (10 * M) / 128;   // 96, 160

    // layer1 merged: hero [6M x 512, K=128], board [10M x 512, K=192]
    {
        GemmP ph = { ah + A_HEROIN, al + A_HEROIN, wh + W_HW1, hb1, 512,
                     ah + A_HEROH, al + A_HEROH, 128, 0, 512, 0, yh1 };
        GemmP pb = { ah + A_BOARDIN, al + A_BOARDIN, wh + W_BW1, bb1, 512,
                     ah + A_BOARDH, al + A_BOARDH, 192, 0, 512, 0, yb1 };
        hmma_gemm<128><<<dim3(4, yh1 + yb1), 256, SMEM128>>>(ph, pb);
    }
    // layer2 merged: hero [6M x 128, K=512] -> X scatter; board [10M x 128] -> X
    {
        GemmP ph = { ah + A_HEROH, al + A_HEROH, wh + W_HW2, hb2, 128,
                     ah + A_X, al + A_X, 512, 6, 2048, 0, yh1 };
        GemmP pb = { ah + A_BOARDH, al + A_BOARDH, wh + W_BW2, bb2, 128,
                     ah + A_X, al + A_X, 512, 10, 2048, 768, yb1 };
        hmma_gemm<128><<<dim3(1, yh1 + yb1), 256, SMEM128>>>(ph, pb);
    }
    // o1: [M x 512], K=2048, BM=32 -> 256 CTAs
    {
        GemmP p = { ah + A_X, al + A_X, wh + W_WF, ob1, 512,
                    ah + A_O1, al + A_O1, 2048, 0, 512, 0, M / 32 };
        hmma_gemm<32><<<dim3(4, M / 32), 256, SMEM32>>>(p, p);
    }
    // o2: [M x 256], K=512
    {
        GemmP p = { ah + A_O1, al + A_O1, wh + W_OW2, ob2, 256,
                    ah + A_O2, al + A_O2, 512, 0, 256, 0, M / 32 };
        hmma_gemm<32><<<dim3(2, M / 32), 256, SMEM32>>>(p, p);
    }
    // o3: [M x 128 (127 real)], K=256
    {
        GemmP p = { ah + A_O2, al + A_O2, wh + W_OW3, ob3, 127,
                    ah + A_O3, al + A_O3, 256, 0, 128, 0, M / 32 };
        hmma_gemm<32><<<dim3(1, M / 32), 256, SMEM32>>>(p, p);
    }

    final_kernel<<<M, 32>>>(ah + A_O3, al + A_O3, sW, sb, out);
    (void)out_size; (void)n_in;
}

// round 5
// speedup vs baseline: 5.9876x; 1.3990x over previous
#include <cuda_runtime.h>
#include <cuda_fp16.h>
#include <cstddef>
#include <cstdint>

// ============================================================================
// SmalldeckClassificationFlat — pure fp16 HMMA pipeline (1-term).
//   All GEMMs: C = lrelu(A(fp16) @ B(fp16)^T + bias), fp32 accumulate.
//   cp.async 3-stage ring + ldmatrix(.x4 for B) + mma.m16n8k16.
//   Merged dual-segment launches; split-K for o1 (K=2048).
// ============================================================================

#define EMBD 64
static constexpr int MAXM = 2048;

// --------------------- activation scratch (fp16) ----------------------------
static constexpr size_t A_HEROIN  = 0;
static constexpr size_t S_HEROIN  = (size_t)MAXM * 6 * 128;
static constexpr size_t A_BOARDIN = A_HEROIN + S_HEROIN;
static constexpr size_t S_BOARDIN = (size_t)MAXM * 10 * 192;
static constexpr size_t A_HEROH   = A_BOARDIN + S_BOARDIN;
static constexpr size_t S_HEROH   = (size_t)MAXM * 6 * 512;
static constexpr size_t A_BOARDH  = A_HEROH + S_HEROH;
static constexpr size_t S_BOARDH  = (size_t)MAXM * 10 * 512;
static constexpr size_t A_X       = A_BOARDH + S_BOARDH;
static constexpr size_t S_X       = (size_t)MAXM * 2048;
static constexpr size_t A_O1      = A_X + S_X;
static constexpr size_t S_O1      = (size_t)MAXM * 512;
static constexpr size_t A_O2      = A_O1 + S_O1;
static constexpr size_t S_O2      = (size_t)MAXM * 256;
static constexpr size_t A_O3      = A_O2 + S_O2;
static constexpr size_t S_O3      = (size_t)MAXM * 128;
static constexpr size_t A_TOT     = A_O3 + S_O3;
__device__ __align__(256) __half g_ah[A_TOT];

// --------------------------- weight scratch (fp16) --------------------------
static constexpr size_t W_HW1 = 0;                       // 512x128
static constexpr size_t W_HW2 = W_HW1 + 512 * 128;       // 128x512
static constexpr size_t W_BW1 = W_HW2 + 128 * 512;       // 512x192
static constexpr size_t W_BW2 = W_BW1 + 512 * 192;       // 128x512
static constexpr size_t W_WF  = W_BW2 + 128 * 512;       // 512x2048 (fold, fused)
static constexpr size_t W_OW2 = W_WF  + 512 * 2048;      // 256x512
static constexpr size_t W_OW3 = W_OW2 + 256 * 512;       // 128x256 (row 127 zero)
static constexpr size_t W_TOT = W_OW3 + 128 * 256;
__device__ __align__(256) __half g_wh[W_TOT];

// split-K partials for o1: 2 x [2048 x 512] fp32
__device__ __align__(256) float g_part[2 * MAXM * 512];

__constant__ int HP[6][2]  = {{0,1},{0,2},{0,3},{1,2},{1,3},{2,3}};
__constant__ int BT[10][3] = {{0,1,2},{0,1,3},{0,1,4},{0,2,3},{0,2,4},
                              {0,3,4},{1,2,3},{1,2,4},{1,3,4},{2,3,4}};

// ------------------------------ PTX helpers ---------------------------------
__device__ __forceinline__ uint32_t smem_to_u32(const void* p) {
    uint32_t a;
    asm("{ .reg .u64 t; cvta.to.shared.u64 t, %1; cvt.u32.u64 %0, t; }" : "=r"(a) : "l"(p));
    return a;
}
__device__ __forceinline__ void cp_async16(uint32_t dst, const void* src) {
    asm volatile("cp.async.cg.shared.global [%0], [%1], 16;\n" :: "r"(dst), "l"(src));
}
__device__ __forceinline__ void cp_commit() {
    asm volatile("cp.async.commit_group;\n" ::: "memory");
}
template <int N>
__device__ __forceinline__ void cp_wait() {
    asm volatile("cp.async.wait_group %0;\n" :: "n"(N) : "memory");
}
__device__ __forceinline__ void ldm4(uint32_t (&r)[4], uint32_t a) {
    asm volatile("ldmatrix.sync.aligned.m8n8.x4.shared.b16 {%0,%1,%2,%3}, [%4];"
                 : "=r"(r[0]), "=r"(r[1]), "=r"(r[2]), "=r"(r[3]) : "r"(a));
}
__device__ __forceinline__ void mma16816(float (&d)[4], const uint32_t (&a)[4],
                                         uint32_t b0, uint32_t b1) {
    asm volatile(
        "mma.sync.aligned.m16n8k16.row.col.f32.f16.f16.f32 "
        "{%0,%1,%2,%3}, {%4,%5,%6,%7}, {%8,%9}, {%0,%1,%2,%3};"
        : "+f"(d[0]), "+f"(d[1]), "+f"(d[2]), "+f"(d[3])
        : "r"(a[0]), "r"(a[1]), "r"(a[2]), "r"(a[3]), "r"(b0), "r"(b1));
}

// ----------------------------------------------------------------------------
// prep: sort cards, gather embeddings, emit fp16 inputs
// ----------------------------------------------------------------------------
__global__ void prep_kernel(const int* __restrict__ x, const float* __restrict__ emb,
                            __half* __restrict__ ah)
{
    int m = blockIdx.x;
    int t = threadIdx.x;  // 64
    __shared__ int   cid[9];
    __shared__ float e9[9][EMBD];

    if (t == 0) {
        int key[9], c[9];
        #pragma unroll
        for (int i = 0; i < 9; i++) {
            int rk = x[m * 18 + 2 * i];
            int st = x[m * 18 + 2 * i + 1];
            key[i] = rk * 8 + st;
            c[i]   = (rk - 1) * st;
        }
        for (int i = 1; i < 4; i++) {
            int k = key[i], v = c[i], j = i - 1;
            while (j >= 0 && key[j] > k) { key[j+1] = key[j]; c[j+1] = c[j]; j--; }
            key[j+1] = k; c[j+1] = v;
        }
        for (int i = 5; i < 9; i++) {
            int k = key[i], v = c[i], j = i - 1;
            while (j >= 4 && key[j] > k) { key[j+1] = key[j]; c[j+1] = c[j]; j--; }
            key[j+1] = k; c[j+1] = v;
        }
        #pragma unroll
        for (int i = 0; i < 9; i++) cid[i] = c[i];
    }
    __syncthreads();

    #pragma unroll
    for (int i = 0; i < 9; i++) e9[i][t] = emb[cid[i] * EMBD + t];

    #pragma unroll
    for (int hh = 0; hh < 6; hh++) {
        size_t base = A_HEROIN + ((size_t)m * 6 + hh) * 128;
        ah[base + t]      = __float2half_rn(e9[HP[hh][0]][t]);
        ah[base + 64 + t] = __float2half_rn(e9[HP[hh][1]][t]);
    }
    #pragma unroll
    for (int b = 0; b < 10; b++) {
        size_t base = A_BOARDIN + ((size_t)m * 10 + b) * 192;
        ah[base + t]       = __float2half_rn(e9[4 + BT[b][0]][t]);
        ah[base + 64 + t]  = __float2half_rn(e9[4 + BT[b][1]][t]);
        ah[base + 128 + t] = __float2half_rn(e9[4 + BT[b][2]][t]);
    }
}

// ----------------------------------------------------------------------------
// fold+split fused: Wfold[r][n] = grouped sums of oW1 -> fp16 transposed
// into g_wh[W_WF + n*2048 + r]. Tiles 32(r) x 32(n).
// ----------------------------------------------------------------------------
__global__ void fold_split_kernel(const float* __restrict__ oW1, __half* __restrict__ dh)
{
    int r0 = blockIdx.x * 32, n0 = blockIdx.y * 32;
    int tx = threadIdx.x, ty = threadIdx.y;
    __shared__ float t[32][33];
    #pragma unroll
    for (int j = 0; j < 4; j++) {
        int r = r0 + ty + 8 * j;
        int n = n0 + tx;
        float s = 0.f;
        if (r < 768) {
            int h = r >> 7, k = r & 127;
            #pragma unroll
            for (int b = 0; b < 10; b++)
                s += oW1[((size_t)((h * 10 + b) * 256 + k)) * 512 + n];
        } else {
            int rb = r - 768;
            int b = rb >> 7, k = rb & 127;
            #pragma unroll
            for (int h = 0; h < 6; h++)
                s += oW1[((size_t)((h * 10 + b) * 256 + 128 + k)) * 512 + n];
        }
        t[ty + 8 * j][tx] = s;
    }
    __syncthreads();
    #pragma unroll
    for (int j = 0; j < 4; j++) {
        int nl = ty + 8 * j;
        dh[W_WF + (size_t)(n0 + nl) * 2048 + r0 + tx] = __float2half_rn(t[tx][nl]);
    }
}

// ----------------------------------------------------------------------------
// wsplit: W[K][N] fp32 -> [Npad][K] fp16 transposed (rows >= N zeroed)
// ----------------------------------------------------------------------------
struct TD { const float* src; __half* dh; int K, N, Npad; };
struct TDArr { TD d[6]; };

__global__ void wsplit_kernel(TDArr descs)
{
    TD d = descs.d[blockIdx.z];
    int kt = blockIdx.x * 32, nt = blockIdx.y * 32;
    if (kt >= d.K || nt >= d.Npad) return;
    __shared__ float tile[32][33];
    for (int i = threadIdx.y; i < 32; i += 8) {
        int k = kt + i, n = nt + threadIdx.x;
        float v = (k < d.K && n < d.N) ? d.src[(size_t)k * d.N + n] : 0.f;
        tile[i][threadIdx.x] = v;
    }
    __syncthreads();
    for (int i = threadIdx.y; i < 32; i += 8) {
        int n = nt + i, k = kt + threadIdx.x;
        if (n < d.Npad && k < d.K)
            d.dh[(size_t)n * d.K + k] = __float2half_rn(tile[threadIdx.x][i]);
    }
}

// ----------------------------------------------------------------------------
// HMMA GEMM (pure fp16): C = lrelu(A @ B^T + bias) or fp32 partial (split-K).
// BN=128, BK=32, 8 warps as (BM/32) M-warps x NWARP N-warps, warp tile 32 x WN.
// 3-stage cp.async ring, ldmatrix.x4 for both A and B.
// Scatter: divv==0 -> r*ldOut ; else (r/divv)*ldOut + seg + (r%divv)*128.
// Split-K: kbeg = blockIdx.z * kcnt, partial out Cp + z*pstride.
// ----------------------------------------------------------------------------
struct GemmP {
    const __half* Ah; const __half* Bh;
    const float* bias; int nbias;
    __half* Ch; float* Cp;
    int Kst;      // row stride of A and B (full K)
    int kcnt;     // K elements this CTA processes
    int divv, ldOut, seg, yb;
    size_t pstride;  // partial buffer stride per z
};

template<int BM>
__global__ void __launch_bounds__(256, 2) hmma_gemm(GemmP p0, GemmP p1)
{
    constexpr int ROWB = 80;              // 32 fp16 (64B) + 16B pad
    constexpr int SA = BM * ROWB;
    constexpr int SB = 128 * ROWB;
    constexpr int STG = SA + SB;
    constexpr int MW = BM / 32;           // M-warps
    constexpr int NWARP = 8 / MW;         // N-warps
    constexpr int WN = 128 / NWARP;       // cols per warp
    constexpr int NF = WN / 8;            // n8 frags per warp
    constexpr int MF = 2;                 // 16-row frags per warp (32 rows)

    bool first = (blockIdx.y < (unsigned)p0.yb);
    GemmP p = first ? p0 : p1;
    int my = first ? blockIdx.y : (blockIdx.y - p0.yb);

    extern __shared__ char smem[];
    uint32_t sbase = smem_to_u32(smem);

    int tid = threadIdx.x, lane = tid & 31, wid = tid >> 5;
    int wy = wid / NWARP, wx = wid % NWARP;
    int m0 = my * BM, n0 = blockIdx.x * 128;
    int Kst = p.Kst;
    int kbeg = blockIdx.z * p.kcnt;

    float acc[MF][NF][4];
    #pragma unroll
    for (int i = 0; i < MF; i++)
        #pragma unroll
        for (int j = 0; j < NF; j++)
            #pragma unroll
            for (int q = 0; q < 4; q++) acc[i][j][q] = 0.f;

    auto load_stage = [&](int k0, int st) {
        uint32_t s0 = sbase + (uint32_t)st * STG;
        for (int i = tid; i < BM * 4; i += 256) {
            int row = i >> 2, c = i & 3;
            size_t go = (size_t)(m0 + row) * Kst + kbeg + k0 + c * 8;
            cp_async16(s0 + row * ROWB + c * 16, p.Ah + go);
        }
        for (int i = tid; i < 512; i += 256) {
            int row = i >> 2, c = i & 3;
            size_t go = (size_t)(n0 + row) * Kst + kbeg + k0 + c * 8;
            cp_async16(s0 + SA + row * ROWB + c * 16, p.Bh + go);
        }
    };

    // A: lanes 0-15 rows, lanes 16-31 shift 16B (k8-15) -> frag order a0..a3
    uint32_t a_off = (uint32_t)((wy * 32 + (lane & 15)) * ROWB + (lane >> 4) * 16);
    // B x4: lanes>>3 groups at 16B steps -> r0=k0-7, r1=k8-15, r2=k16-23, r3=k24-31
    uint32_t b_off = (uint32_t)(SA + (wx * WN + (lane & 7)) * ROWB + ((lane >> 3) & 3) * 16);

    int nch = p.kcnt >> 5;
    load_stage(0, 0);
    cp_commit();
    if (nch > 1) load_stage(32, 1);
    cp_commit();

    for (int ch = 0; ch < nch; ch++) {
        cp_wait<1>();
        __syncthreads();
        if (ch + 2 < nch) load_stage((ch + 2) << 5, (ch + 2) % 3);
        cp_commit();

        uint32_t s0 = sbase + (uint32_t)(ch % 3) * STG;

        uint32_t bf[NF][4];
        #pragma unroll
        for (int ni = 0; ni < NF; ni++)
            ldm4(bf[ni], s0 + b_off + ni * (8 * ROWB));

        #pragma unroll
        for (int k16 = 0; k16 < 2; k16++) {
            #pragma unroll
            for (int mi = 0; mi < MF; mi++) {
                uint32_t af[4];
                ldm4(af, s0 + a_off + mi * (16 * ROWB) + k16 * 32);
                #pragma unroll
                for (int ni = 0; ni < NF; ni++)
                    mma16816(acc[mi][ni], af, bf[ni][2 * k16], bf[ni][2 * k16 + 1]);
            }
        }
    }

    // ---- epilogue ----
    #pragma unroll
    for (int mi = 0; mi < MF; mi++) {
        #pragma unroll
        for (int ni = 0; ni < NF; ni++) {
            int n = n0 + wx * WN + ni * 8 + 2 * (lane & 3);
            #pragma unroll
            for (int half = 0; half < 2; half++) {
                int r = m0 + wy * 32 + mi * 16 + (lane >> 2) + half * 8;
                float v0 = acc[mi][ni][half * 2 + 0];
                float v1 = acc[mi][ni][half * 2 + 1];
                if (p.Cp) {
                    float2 pv = make_float2(v0, v1);
                    *reinterpret_cast<float2*>(p.Cp + blockIdx.z * p.pstride
                        + (size_t)r * p.ldOut + n) = pv;
                } else {
                    float bv0 = (n < p.nbias) ? p.bias[n] : 0.f;
                    float bv1 = (n + 1 < p.nbias) ? p.bias[n + 1] : 0.f;
                    v0 += bv0; v1 += bv1;
                    v0 = (v0 > 0.f) ? v0 : 0.01f * v0;
                    v1 = (v1 > 0.f) ? v1 : 0.01f * v1;
                    size_t base;
                    if (p.divv == 0) base = (size_t)r * p.ldOut + n;
                    else base = (size_t)(r / p.divv) * p.ldOut + p.seg
                              + (size_t)(r % p.divv) * 128 + n;
                    __half2 hv = __floats2half2_rn(v0, v1);
                    *reinterpret_cast<__half2*>(p.Ch + base) = hv;
                }
            }
        }
    }
}

// ----------------------------------------------------------------------------
// reduce for o1 split-K: O1 = lrelu(p0 + p1 + bias) -> fp16
// ----------------------------------------------------------------------------
__global__ void reduce_o1_kernel(const float* __restrict__ Cp, const float* __restrict__ bias,
                                 __half* __restrict__ O1, size_t pstride, int total)
{
    int i = blockIdx.x * 256 + threadIdx.x;
    if (i >= total) return;
    float v = Cp[i] + Cp[i + pstride] + bias[i & 511];
    v = (v > 0.f) ? v : 0.01f * v;
    O1[i] = __float2half_rn(v);
}

// ----------------------------------------------------------------------------
// final scorer: out[m] = O3[m](127) @ sW + sb
// ----------------------------------------------------------------------------
__global__ void final_kernel(const __half* __restrict__ O3h,
                             const float* __restrict__ sW,
                             const float* __restrict__ sb, float* __restrict__ out)
{
    int m = blockIdx.x;
    __shared__ float row[127];
    for (int k = threadIdx.x; k < 127; k += 32)
        row[k] = __half2float(O3h[(size_t)m * 128 + k]);
    __syncwarp();
    if (threadIdx.x < 9) {
        int n = threadIdx.x;
        float acc = sb[n];
        #pragma unroll 1
        for (int k = 0; k < 127; k++) acc += row[k] * sW[k * 9 + n];
        out[(size_t)m * 9 + n] = acc;
    }
}

// ----------------------------------------------------------------------------
extern "C" void kernel_launch(void* const* d_in, const int* in_sizes, int n_in,
                              void* d_out, int out_size)
{
    const int*   x   = (const int*)  d_in[0];
    const float* emb = (const float*)d_in[1];
    const float* hW1 = (const float*)d_in[2];
    const float* hb1 = (const float*)d_in[3];
    const float* hW2 = (const float*)d_in[4];
    const float* hb2 = (const float*)d_in[5];
    const float* bW1 = (const float*)d_in[6];
    const float* bb1 = (const float*)d_in[7];
    const float* bW2 = (const float*)d_in[8];
    const float* bb2 = (const float*)d_in[9];
    const float* oW1 = (const float*)d_in[10];
    const float* ob1 = (const float*)d_in[11];
    const float* oW2 = (const float*)d_in[12];
    const float* ob2 = (const float*)d_in[13];
    const float* oW3 = (const float*)d_in[14];
    const float* ob3 = (const float*)d_in[15];
    const float* sW  = (const float*)d_in[16];
    const float* sb  = (const float*)d_in[17];
    float* out = (float*)d_out;

    int M = in_sizes[0] / 18;
    if (M > MAXM) M = MAXM;

    __half *ah = nullptr, *wh = nullptr;
    float* part = nullptr;
    cudaGetSymbolAddress((void**)&ah, g_ah);
    cudaGetSymbolAddress((void**)&wh, g_wh);
    cudaGetSymbolAddress((void**)&part, g_part);

    constexpr int SMEM128 = 3 * (128 + 128) * 80;   // 61440
    constexpr int SMEM64  = 3 * (64 + 128) * 80;    // 46080
    constexpr int SMEM32  = 3 * (32 + 128) * 80;    // 38400
    cudaFuncSetAttribute(hmma_gemm<128>, cudaFuncAttributeMaxDynamicSharedMemorySize, SMEM128);
    cudaFuncSetAttribute(hmma_gemm<64>,  cudaFuncAttributeMaxDynamicSharedMemorySize, SMEM64);
    cudaFuncSetAttribute(hmma_gemm<32>,  cudaFuncAttributeMaxDynamicSharedMemorySize, SMEM32);

    prep_kernel<<<M, 64>>>(x, emb, ah);
    fold_split_kernel<<<dim3(64, 16), dim3(32, 8)>>>(oW1, wh);

    TDArr td;
    td.d[0] = { hW1, wh + W_HW1, 128, 512, 512 };
    td.d[1] = { hW2, wh + W_HW2, 512, 128, 128 };
    td.d[2] = { bW1, wh + W_BW1, 192, 512, 512 };
    td.d[3] = { bW2, wh + W_BW2, 512, 128, 128 };
    td.d[4] = { oW2, wh + W_OW2, 512, 256, 256 };
    td.d[5] = { oW3, wh + W_OW3, 256, 127, 128 };
    wsplit_kernel<<<dim3(64, 16, 6), dim3(32, 8)>>>(td);

    int yh1 = (6 * M) / 128, yb1 = (10 * M) / 128;   // 96, 160

    // layer1 merged: hero [6M x 512, K=128], board [10M x 512, K=192]
    {
        GemmP ph = { ah + A_HEROIN, wh + W_HW1, hb1, 512, ah + A_HEROH, nullptr,
                     128, 128, 0, 512, 0, yh1, 0 };
        GemmP pb = { ah + A_BOARDIN, wh + W_BW1, bb1, 512, ah + A_BOARDH, nullptr,
                     192, 192, 0, 512, 0, yb1, 0 };
        hmma_gemm<128><<<dim3(4, yh1 + yb1), 256, SMEM128>>>(ph, pb);
    }
    // layer2 merged: hero/board [.. x 128, K=512] -> X scatter
    {
        GemmP ph = { ah + A_HEROH, wh + W_HW2, hb2, 128, ah + A_X, nullptr,
                     512, 512, 6, 2048, 0, yh1, 0 };
        GemmP pb = { ah + A_BOARDH, wh + W_BW2, bb2, 128, ah + A_X, nullptr,
                     512, 512, 10, 2048, 768, yb1, 0 };
        hmma_gemm<128><<<dim3(1, yh1 + yb1), 256, SMEM128>>>(ph, pb);
    }
    // o1: [M x 512], K=2048, split-K=2, BM=64, fp32 partials
    {
        GemmP p = { ah + A_X, wh + W_WF, nullptr, 0, nullptr, part,
                    2048, 1024, 0, 512, 0, M / 64, (size_t)M * 512 };
        hmma_gemm<64><<<dim3(4, M / 64, 2), 256, SMEM64>>>(p, p);
        int total = M * 512;
        reduce_o1_kernel<<<(total + 255) / 256, 256>>>(part, ob1, ah + A_O1,
                                                       (size_t)M * 512, total);
    }
    // o2: [M x 256], K=512, BM=32
    {
        GemmP p = { ah + A_O1, wh + W_OW2, ob2, 256, ah + A_O2, nullptr,
                    512, 512, 0, 256, 0, M / 32, 0 };
        hmma_gemm<32><<<dim3(2, M / 32), 256, SMEM32>>>(p, p);
    }
    // o3: [M x 128 (127 real)], K=256, BM=32
    {
        GemmP p = { ah + A_O2, wh + W_OW3, ob3, 127, ah + A_O3, nullptr,
                    256, 256, 0, 128, 0, M / 32, 0 };
        hmma_gemm<32><<<dim3(1, M / 32), 256, SMEM32>>>(p, p);
    }

    final_kernel<<<M, 32>>>(ah + A_O3, sW, sb, out);
    (void)out_size; (void)n_in;
}

// round 12
// speedup vs baseline: 6.2506x; 1.0439x over previous
#include <cuda_runtime.h>
#include <cuda_fp16.h>
#include <cstddef>
#include <cstdint>

// ============================================================================
// SmalldeckClassificationFlat — fp16 HMMA, 128-thread CTAs, 4 CTAs/SM.
//   All GEMMs: C = lrelu(A(fp16) @ B(fp16)^T + bias), fp32 accumulate.
//   cp.async 3-stage ring (BK=32) + ldmatrix.x4 + mma.m16n8k16.
//   Final 127->9 scorer fused into o3 epilogue. Split-K=4 for o1.
// ============================================================================

#define EMBD 64
static constexpr int MAXM = 2048;

// --------------------- activation scratch (fp16) ----------------------------
static constexpr size_t A_HEROIN  = 0;
static constexpr size_t S_HEROIN  = (size_t)MAXM * 6 * 128;
static constexpr size_t A_BOARDIN = A_HEROIN + S_HEROIN;
static constexpr size_t S_BOARDIN = (size_t)MAXM * 10 * 192;
static constexpr size_t A_HEROH   = A_BOARDIN + S_BOARDIN;
static constexpr size_t S_HEROH   = (size_t)MAXM * 6 * 512;
static constexpr size_t A_BOARDH  = A_HEROH + S_HEROH;
static constexpr size_t S_BOARDH  = (size_t)MAXM * 10 * 512;
static constexpr size_t A_X       = A_BOARDH + S_BOARDH;
static constexpr size_t S_X       = (size_t)MAXM * 2048;
static constexpr size_t A_O1      = A_X + S_X;
static constexpr size_t S_O1      = (size_t)MAXM * 512;
static constexpr size_t A_O2      = A_O1 + S_O1;
static constexpr size_t S_O2      = (size_t)MAXM * 256;
static constexpr size_t A_TOT     = A_O2 + S_O2;
__device__ __align__(256) __half g_ah[A_TOT];

// --------------------------- weight scratch (fp16) --------------------------
static constexpr size_t W_HW1 = 0;                       // 512x128
static constexpr size_t W_HW2 = W_HW1 + 512 * 128;       // 128x512
static constexpr size_t W_BW1 = W_HW2 + 128 * 512;       // 512x192
static constexpr size_t W_BW2 = W_BW1 + 512 * 192;       // 128x512
static constexpr size_t W_WF  = W_BW2 + 128 * 512;       // 512x2048 (fold, fused)
static constexpr size_t W_OW2 = W_WF  + 512 * 2048;      // 256x512
static constexpr size_t W_OW3 = W_OW2 + 256 * 512;       // 128x256 (row 127 zero)
static constexpr size_t W_TOT = W_OW3 + 128 * 256;
__device__ __align__(256) __half g_wh[W_TOT];

// split-K partials for o1: 4 x [2048 x 512] fp32
__device__ __align__(256) float g_part[4 * MAXM * 512];

__constant__ int HP[6][2]  = {{0,1},{0,2},{0,3},{1,2},{1,3},{2,3}};
__constant__ int BT[10][3] = {{0,1,2},{0,1,3},{0,1,4},{0,2,3},{0,2,4},
                              {0,3,4},{1,2,3},{1,2,4},{1,3,4},{2,3,4}};

// ------------------------------ PTX helpers ---------------------------------
__device__ __forceinline__ uint32_t smem_to_u32(const void* p) {
    uint32_t a;
    asm("{ .reg .u64 t; cvta.to.shared.u64 t, %1; cvt.u32.u64 %0, t; }" : "=r"(a) : "l"(p));
    return a;
}
__device__ __forceinline__ void cp_async16(uint32_t dst, const void* src) {
    asm volatile("cp.async.cg.shared.global [%0], [%1], 16;\n" :: "r"(dst), "l"(src));
}
__device__ __forceinline__ void cp_commit() {
    asm volatile("cp.async.commit_group;\n" ::: "memory");
}
template <int N>
__device__ __forceinline__ void cp_wait() {
    asm volatile("cp.async.wait_group %0;\n" :: "n"(N) : "memory");
}
__device__ __forceinline__ void ldm4(uint32_t (&r)[4], uint32_t a) {
    asm volatile("ldmatrix.sync.aligned.m8n8.x4.shared.b16 {%0,%1,%2,%3}, [%4];"
                 : "=r"(r[0]), "=r"(r[1]), "=r"(r[2]), "=r"(r[3]) : "r"(a));
}
__device__ __forceinline__ void mma16816(float (&d)[4], const uint32_t (&a)[4],
                                         uint32_t b0, uint32_t b1) {
    asm volatile(
        "mma.sync.aligned.m16n8k16.row.col.f32.f16.f16.f32 "
        "{%0,%1,%2,%3}, {%4,%5,%6,%7}, {%8,%9}, {%0,%1,%2,%3};"
        : "+f"(d[0]), "+f"(d[1]), "+f"(d[2]), "+f"(d[3])
        : "r"(a[0]), "r"(a[1]), "r"(a[2]), "r"(a[3]), "r"(b0), "r"(b1));
}

// ----------------------------------------------------------------------------
// prep: 4 rows per block (256 threads), sort cards, gather embeddings -> fp16
// ----------------------------------------------------------------------------
__global__ void prep_kernel(const int* __restrict__ x, const float* __restrict__ emb,
                            __half* __restrict__ ah)
{
    int t  = threadIdx.x;
    int lr = t >> 6;           // 0..3 local row
    int c  = t & 63;           // embedding column
    int m  = blockIdx.x * 4 + lr;

    __shared__ int   cid[4][9];
    __shared__ float e9[4][9][EMBD];

    if (c == 0) {
        int key[9], cc[9];
        #pragma unroll
        for (int i = 0; i < 9; i++) {
            int rk = x[m * 18 + 2 * i];
            int st = x[m * 18 + 2 * i + 1];
            key[i] = rk * 8 + st;
            cc[i]  = (rk - 1) * st;
        }
        for (int i = 1; i < 4; i++) {
            int k = key[i], v = cc[i], j = i - 1;
            while (j >= 0 && key[j] > k) { key[j+1] = key[j]; cc[j+1] = cc[j]; j--; }
            key[j+1] = k; cc[j+1] = v;
        }
        for (int i = 5; i < 9; i++) {
            int k = key[i], v = cc[i], j = i - 1;
            while (j >= 4 && key[j] > k) { key[j+1] = key[j]; cc[j+1] = cc[j]; j--; }
            key[j+1] = k; cc[j+1] = v;
        }
        #pragma unroll
        for (int i = 0; i < 9; i++) cid[lr][i] = cc[i];
    }
    __syncthreads();

    #pragma unroll
    for (int i = 0; i < 9; i++) e9[lr][i][c] = emb[cid[lr][i] * EMBD + c];
    // each thread reads only its own (lr, c) column below -> no extra sync

    #pragma unroll
    for (int hh = 0; hh < 6; hh++) {
        size_t base = A_HEROIN + ((size_t)m * 6 + hh) * 128;
        ah[base + c]      = __float2half_rn(e9[lr][HP[hh][0]][c]);
        ah[base + 64 + c] = __float2half_rn(e9[lr][HP[hh][1]][c]);
    }
    #pragma unroll
    for (int b = 0; b < 10; b++) {
        size_t base = A_BOARDIN + ((size_t)m * 10 + b) * 192;
        ah[base + c]       = __float2half_rn(e9[lr][4 + BT[b][0]][c]);
        ah[base + 64 + c]  = __float2half_rn(e9[lr][4 + BT[b][1]][c]);
        ah[base + 128 + c] = __float2half_rn(e9[lr][4 + BT[b][2]][c]);
    }
}

// ----------------------------------------------------------------------------
// prep_w: z<6 -> transpose+fp16 weight; z==6 -> fused fold of oW1 into W_WF
// ----------------------------------------------------------------------------
struct TD { const float* src; __half* dh; int K, N, Npad; };
struct TDArr { TD d[6]; };

__global__ void prep_w_kernel(TDArr descs, const float* __restrict__ oW1,
                              __half* __restrict__ whBase)
{
    int tx = threadIdx.x, ty = threadIdx.y;
    if (blockIdx.z == 6) {
        // fold: Wfold[r][n] -> wh[W_WF + n*2048 + r]
        int r0 = blockIdx.x * 32, n0 = blockIdx.y * 32;
        __shared__ float t[32][33];
        #pragma unroll
        for (int j = 0; j < 4; j++) {
            int r = r0 + ty + 8 * j;
            int n = n0 + tx;
            float s = 0.f;
            if (r < 768) {
                int h = r >> 7, k = r & 127;
                #pragma unroll
                for (int b = 0; b < 10; b++)
                    s += oW1[((size_t)((h * 10 + b) * 256 + k)) * 512 + n];
            } else {
                int rb = r - 768;
                int b = rb >> 7, k = rb & 127;
                #pragma unroll
                for (int h = 0; h < 6; h++)
                    s += oW1[((size_t)((h * 10 + b) * 256 + 128 + k)) * 512 + n];
            }
            t[ty + 8 * j][tx] = s;
        }
        __syncthreads();
        #pragma unroll
        for (int j = 0; j < 4; j++) {
            int nl = ty + 8 * j;
            whBase[W_WF + (size_t)(n0 + nl) * 2048 + r0 + tx] = __float2half_rn(t[tx][nl]);
        }
    } else {
        TD d = descs.d[blockIdx.z];
        int kt = blockIdx.x * 32, nt = blockIdx.y * 32;
        if (kt >= d.K || nt >= d.Npad) return;
        __shared__ float tile[32][33];
        for (int i = ty; i < 32; i += 8) {
            int k = kt + i, n = nt + tx;
            float v = (k < d.K && n < d.N) ? d.src[(size_t)k * d.N + n] : 0.f;
            tile[i][tx] = v;
        }
        __syncthreads();
        for (int i = ty; i < 32; i += 8) {
            int n = nt + i, k = kt + tx;
            if (n < d.Npad && k < d.K)
                d.dh[(size_t)n * d.K + k] = __float2half_rn(tile[tx][i]);
        }
    }
}

// ----------------------------------------------------------------------------
// HMMA GEMM, 128 threads (4 warps), BN=128, BK=32, 3-stage cp.async ring.
// BM=64: warps 2Mx2N (warp 32x64); BM=32: 1Mx4N (warp 32x32).
// FINAL: fuse o3 epilogue + 127->9 scorer (writes fp32 out).
// ----------------------------------------------------------------------------
struct GemmP {
    const __half* Ah; const __half* Bh;
    const float* bias; int nbias;
    __half* Ch; float* Cp;
    int Kst;      // row stride of A and B (full K)
    int kcnt;     // K elements this CTA processes
    int divv, ldOut, seg, yb;
    size_t pstride;
    const float* sW; const float* sb; float* outp;
};

template<int BM, bool FINAL>
__global__ void __launch_bounds__(128, 4) hmma_gemm(GemmP p0, GemmP p1)
{
    constexpr int ROWB = 80;              // 32 fp16 (64B) + 16B pad
    constexpr int SA = BM * ROWB;
    constexpr int SB = 128 * ROWB;
    constexpr int STG = SA + SB;
    constexpr int MW = BM / 32;           // M-warps (2 or 1)
    constexpr int NWARP = 4 / MW;         // N-warps (2 or 4)
    constexpr int WN = 128 / NWARP;       // cols per warp (64 or 32)
    constexpr int NF = WN / 8;            // n8 frags (8 or 4)
    constexpr int MF = 2;

    bool first = (blockIdx.y < (unsigned)p0.yb);
    GemmP p = first ? p0 : p1;
    int my = first ? blockIdx.y : (blockIdx.y - p0.yb);

    extern __shared__ char smem[];
    uint32_t sbase = smem_to_u32(smem);

    int tid = threadIdx.x, lane = tid & 31, wid = tid >> 5;
    int wy = wid / NWARP, wx = wid % NWARP;
    int m0 = my * BM, n0 = blockIdx.x * 128;
    int Kst = p.Kst;
    int kbeg = blockIdx.z * p.kcnt;

    // FINAL: stage sW/sb into smem beyond the pipeline region
    float* sWs = reinterpret_cast<float*>(smem + 3 * STG);
    float* sbs = sWs + 1143;
    if (FINAL) {
        for (int i = tid; i < 1143; i += 128) sWs[i] = p.sW[i];
        if (tid < 9) sbs[tid] = p.sb[tid];
    }

    float acc[MF][NF][4];
    #pragma unroll
    for (int i = 0; i < MF; i++)
        #pragma unroll
        for (int j = 0; j < NF; j++)
            #pragma unroll
            for (int q = 0; q < 4; q++) acc[i][j][q] = 0.f;

    auto load_stage = [&](int k0, int st) {
        uint32_t s0 = sbase + (uint32_t)st * STG;
        #pragma unroll
        for (int i = tid; i < BM * 4; i += 128) {
            int row = i >> 2, c = i & 3;
            size_t go = (size_t)(m0 + row) * Kst + kbeg + k0 + c * 8;
            cp_async16(s0 + row * ROWB + c * 16, p.Ah + go);
        }
        #pragma unroll
        for (int i = tid; i < 512; i += 128) {
            int row = i >> 2, c = i & 3;
            size_t go = (size_t)(n0 + row) * Kst + kbeg + k0 + c * 8;
            cp_async16(s0 + SA + row * ROWB + c * 16, p.Bh + go);
        }
    };

    uint32_t a_off = (uint32_t)((wy * 32 + (lane & 15)) * ROWB + (lane >> 4) * 16);
    uint32_t b_off = (uint32_t)(SA + (wx * WN + (lane & 7)) * ROWB + ((lane >> 3) & 3) * 16);

    int nch = p.kcnt >> 5;
    load_stage(0, 0);
    cp_commit();
    if (nch > 1) load_stage(32, 1);
    cp_commit();

    for (int ch = 0; ch < nch; ch++) {
        cp_wait<1>();
        __syncthreads();
        if (ch + 2 < nch) load_stage((ch + 2) << 5, (ch + 2) % 3);
        cp_commit();

        uint32_t s0 = sbase + (uint32_t)(ch % 3) * STG;

        uint32_t bf[NF][4];
        #pragma unroll
        for (int ni = 0; ni < NF; ni++)
            ldm4(bf[ni], s0 + b_off + ni * (8 * ROWB));

        #pragma unroll
        for (int k16 = 0; k16 < 2; k16++) {
            #pragma unroll
            for (int mi = 0; mi < MF; mi++) {
                uint32_t af[4];
                ldm4(af, s0 + a_off + mi * (16 * ROWB) + k16 * 32);
                #pragma unroll
                for (int ni = 0; ni < NF; ni++)
                    mma16816(acc[mi][ni], af, bf[ni][2 * k16], bf[ni][2 * k16 + 1]);
            }
        }
    }

    if (FINAL) {
        // o3 epilogue (bias + lrelu) into smem tile, then fused 127->9 scorer
        float* sm = reinterpret_cast<float*>(smem);      // [32][132]
        __syncthreads();                                  // all reads of stages done
        #pragma unroll
        for (int mi = 0; mi < MF; mi++) {
            #pragma unroll
            for (int ni = 0; ni < NF; ni++) {
                int n = wx * WN + ni * 8 + 2 * (lane & 3);
                float bv0 = (n < p.nbias) ? p.bias[n] : 0.f;
                float bv1 = (n + 1 < p.nbias) ? p.bias[n + 1] : 0.f;
                #pragma unroll
                for (int half = 0; half < 2; half++) {
                    int r = mi * 16 + (lane >> 2) + half * 8;
                    float v0 = acc[mi][ni][half * 2 + 0] + bv0;
                    float v1 = acc[mi][ni][half * 2 + 1] + bv1;
                    v0 = (v0 > 0.f) ? v0 : 0.01f * v0;
                    v1 = (v1 > 0.f) ? v1 : 0.01f * v1;
                    sm[r * 132 + n] = v0;
                    sm[r * 132 + n + 1] = v1;
                }
            }
        }
        __syncthreads();
        for (int idx = tid; idx < 32 * 9; idx += 128) {
            int r = idx / 9, n = idx - r * 9;
            float a = sbs[n];
            #pragma unroll 1
            for (int k = 0; k < 127; k++) a += sm[r * 132 + k] * sWs[k * 9 + n];
            p.outp[(size_t)(m0 + r) * 9 + n] = a;
        }
        return;
    }

    // ---- standard epilogue ----
    #pragma unroll
    for (int mi = 0; mi < MF; mi++) {
        #pragma unroll
        for (int ni = 0; ni < NF; ni++) {
            int n = n0 + wx * WN + ni * 8 + 2 * (lane & 3);
            #pragma unroll
            for (int half = 0; half < 2; half++) {
                int r = m0 + wy * 32 + mi * 16 + (lane >> 2) + half * 8;
                float v0 = acc[mi][ni][half * 2 + 0];
                float v1 = acc[mi][ni][half * 2 + 1];
                if (p.Cp) {
                    *reinterpret_cast<float2*>(p.Cp + blockIdx.z * p.pstride
                        + (size_t)r * p.ldOut + n) = make_float2(v0, v1);
                } else {
                    float bv0 = (n < p.nbias) ? p.bias[n] : 0.f;
                    float bv1 = (n + 1 < p.nbias) ? p.bias[n + 1] : 0.f;
                    v0 += bv0; v1 += bv1;
                    v0 = (v0 > 0.f) ? v0 : 0.01f * v0;
                    v1 = (v1 > 0.f) ? v1 : 0.01f * v1;
                    size_t base;
                    if (p.divv == 0) base = (size_t)r * p.ldOut + n;
                    else base = (size_t)(r / p.divv) * p.ldOut + p.seg
                              + (size_t)(r % p.divv) * 128 + n;
                    *reinterpret_cast<__half2*>(p.Ch + base) = __floats2half2_rn(v0, v1);
                }
            }
        }
    }
}

// ----------------------------------------------------------------------------
// reduce for o1 split-K=4: O1 = lrelu(p0+p1+p2+p3 + bias) -> fp16
// ----------------------------------------------------------------------------
__global__ void reduce_o1_kernel(const float* __restrict__ Cp, const float* __restrict__ bias,
                                 __half* __restrict__ O1, size_t pstride, int total)
{
    int i = blockIdx.x * 256 + threadIdx.x;
    if (i >= total) return;
    float v = Cp[i] + Cp[i + pstride] + Cp[i + 2 * pstride] + Cp[i + 3 * pstride]
            + bias[i & 511];
    v = (v > 0.f) ? v : 0.01f * v;
    O1[i] = __float2half_rn(v);
}

// ----------------------------------------------------------------------------
extern "C" void kernel_launch(void* const* d_in, const int* in_sizes, int n_in,
                              void* d_out, int out_size)
{
    const int*   x   = (const int*)  d_in[0];
    const float* emb = (const float*)d_in[1];
    const float* hW1 = (const float*)d_in[2];
    const float* hb1 = (const float*)d_in[3];
    const float* hW2 = (const float*)d_in[4];
    const float* hb2 = (const float*)d_in[5];
    const float* bW1 = (const float*)d_in[6];
    const float* bb1 = (const float*)d_in[7];
    const float* bW2 = (const float*)d_in[8];
    const float* bb2 = (const float*)d_in[9];
    const float* oW1 = (const float*)d_in[10];
    const float* ob1 = (const float*)d_in[11];
    const float* oW2 = (const float*)d_in[12];
    const float* ob2 = (const float*)d_in[13];
    const float* oW3 = (const float*)d_in[14];
    const float* ob3 = (const float*)d_in[15];
    const float* sW  = (const float*)d_in[16];
    const float* sb  = (const float*)d_in[17];
    float* out = (float*)d_out;

    int M = in_sizes[0] / 18;
    if (M > MAXM) M = MAXM;

    __half *ah = nullptr, *wh = nullptr;
    float* part = nullptr;
    cudaGetSymbolAddress((void**)&ah, g_ah);
    cudaGetSymbolAddress((void**)&wh, g_wh);
    cudaGetSymbolAddress((void**)&part, g_part);

    constexpr int SMEM64 = 3 * (64 + 128) * 80;             // 46080
    constexpr int SMEM32 = 3 * (32 + 128) * 80;             // 38400
    constexpr int SMEMF  = SMEM32 + 1152 * 4 + 64;          // + sW/sb staging
    cudaFuncSetAttribute((const void*)hmma_gemm<64, false>,
                         cudaFuncAttributeMaxDynamicSharedMemorySize, SMEM64);
    cudaFuncSetAttribute((const void*)hmma_gemm<32, false>,
                         cudaFuncAttributeMaxDynamicSharedMemorySize, SMEM32);
    cudaFuncSetAttribute((const void*)hmma_gemm<32, true>,
                         cudaFuncAttributeMaxDynamicSharedMemorySize, SMEMF);

    prep_kernel<<<M / 4, 256>>>(x, emb, ah);

    TDArr td;
    td.d[0] = { hW1, wh + W_HW1, 128, 512, 512 };
    td.d[1] = { hW2, wh + W_HW2, 512, 128, 128 };
    td.d[2] = { bW1, wh + W_BW1, 192, 512, 512 };
    td.d[3] = { bW2, wh + W_BW2, 512, 128, 128 };
    td.d[4] = { oW2, wh + W_OW2, 512, 256, 256 };
    td.d[5] = { oW3, wh + W_OW3, 256, 127, 128 };
    prep_w_kernel<<<dim3(64, 16, 7), dim3(32, 8)>>>(td, oW1, wh);

    int yh = (6 * M) / 64, yb = (10 * M) / 64;   // 192, 320

    // layer1 merged: hero [6M x 512, K=128], board [10M x 512, K=192]
    {
        GemmP ph = { ah + A_HEROIN, wh + W_HW1, hb1, 512, ah + A_HEROH, nullptr,
                     128, 128, 0, 512, 0, yh, 0, nullptr, nullptr, nullptr };
        GemmP pb = { ah + A_BOARDIN, wh + W_BW1, bb1, 512, ah + A_BOARDH, nullptr,
                     192, 192, 0, 512, 0, yb, 0, nullptr, nullptr, nullptr };
        hmma_gemm<64, false><<<dim3(4, yh + yb), 128, SMEM64>>>(ph, pb);
    }
    // layer2 merged: hero/board [.. x 128, K=512] -> X scatter
    {
        GemmP ph = { ah + A_HEROH, wh + W_HW2, hb2, 128, ah + A_X, nullptr,
                     512, 512, 6, 2048, 0, yh, 0, nullptr, nullptr, nullptr };
        GemmP pb = { ah + A_BOARDH, wh + W_BW2, bb2, 128, ah + A_X, nullptr,
                     512, 512, 10, 2048, 768, yb, 0, nullptr, nullptr, nullptr };
        hmma_gemm<64, false><<<dim3(1, yh + yb), 128, SMEM64>>>(ph, pb);
    }
    // o1: [M x 512], K=2048, split-K=4, BM=64, fp32 partials
    {
        GemmP p = { ah + A_X, wh + W_WF, nullptr, 0, nullptr, part,
                    2048, 512, 0, 512, 0, M / 64, (size_t)M * 512,
                    nullptr, nullptr, nullptr };
        hmma_gemm<64, false><<<dim3(4, M / 64, 4), 128, SMEM64>>>(p, p);
        int total = M * 512;
        reduce_o1_kernel<<<(total + 255) / 256, 256>>>(part, ob1, ah + A_O1,
                                                       (size_t)M * 512, total);
    }
    // o2: [M x 256], K=512, BM=32
    {
        GemmP p = { ah + A_O1, wh + W_OW2, ob2, 256, ah + A_O2, nullptr,
                    512, 512, 0, 256, 0, M / 32, 0, nullptr, nullptr, nullptr };
        hmma_gemm<32, false><<<dim3(2, M / 32), 128, SMEM32>>>(p, p);
    }
    // o3 + fused scorer: [M x 127] @ oW3 then 127->9, BM=32
    {
        GemmP p = { ah + A_O2, wh + W_OW3, ob3, 127, nullptr, nullptr,
                    256, 256, 0, 128, 0, M / 32, 0, sW, sb, out };
        hmma_gemm<32, true><<<dim3(1, M / 32), 128, SMEMF>>>(p, p);
    }

    (void)out_size; (void)n_in;
}

// round 14
// speedup vs baseline: 6.3268x; 1.0122x over previous
#include <cuda_runtime.h>
#include <cuda_fp16.h>
#include <cstddef>
#include <cstdint>

// ============================================================================
// SmalldeckClassificationFlat — fp16 HMMA, 128-thread CTAs, 4 CTAs/SM.
//   All GEMMs: C = lrelu(A(fp16) @ B(fp16)^T + bias), fp32 accumulate.
//   cp.async 3-stage ring (BK=32) + ldmatrix.x4 + mma.m16n8k16.
//   R13: o1 split-K=2 (BM=32), BM=16 tiles for o2/o3 tails, vectorized reduce.
// ============================================================================

#define EMBD 64
static constexpr int MAXM = 2048;

// --------------------- activation scratch (fp16) ----------------------------
static constexpr size_t A_HEROIN  = 0;
static constexpr size_t S_HEROIN  = (size_t)MAXM * 6 * 128;
static constexpr size_t A_BOARDIN = A_HEROIN + S_HEROIN;
static constexpr size_t S_BOARDIN = (size_t)MAXM * 10 * 192;
static constexpr size_t A_HEROH   = A_BOARDIN + S_BOARDIN;
static constexpr size_t S_HEROH   = (size_t)MAXM * 6 * 512;
static constexpr size_t A_BOARDH  = A_HEROH + S_HEROH;
static constexpr size_t S_BOARDH  = (size_t)MAXM * 10 * 512;
static constexpr size_t A_X       = A_BOARDH + S_BOARDH;
static constexpr size_t S_X       = (size_t)MAXM * 2048;
static constexpr size_t A_O1      = A_X + S_X;
static constexpr size_t S_O1      = (size_t)MAXM * 512;
static constexpr size_t A_O2      = A_O1 + S_O1;
static constexpr size_t S_O2      = (size_t)MAXM * 256;
static constexpr size_t A_TOT     = A_O2 + S_O2;
__device__ __align__(256) __half g_ah[A_TOT];

// --------------------------- weight scratch (fp16) --------------------------
static constexpr size_t W_HW1 = 0;                       // 512x128
static constexpr size_t W_HW2 = W_HW1 + 512 * 128;       // 128x512
static constexpr size_t W_BW1 = W_HW2 + 128 * 512;       // 512x192
static constexpr size_t W_BW2 = W_BW1 + 512 * 192;       // 128x512
static constexpr size_t W_WF  = W_BW2 + 128 * 512;       // 512x2048 (fold, fused)
static constexpr size_t W_OW2 = W_WF  + 512 * 2048;      // 256x512
static constexpr size_t W_OW3 = W_OW2 + 256 * 512;       // 128x256 (row 127 zero)
static constexpr size_t W_TOT = W_OW3 + 128 * 256;
__device__ __align__(256) __half g_wh[W_TOT];

// split-K partials for o1: 2 x [2048 x 512] fp32
__device__ __align__(256) float g_part[2 * MAXM * 512];

__constant__ int HP[6][2]  = {{0,1},{0,2},{0,3},{1,2},{1,3},{2,3}};
__constant__ int BT[10][3] = {{0,1,2},{0,1,3},{0,1,4},{0,2,3},{0,2,4},
                              {0,3,4},{1,2,3},{1,2,4},{1,3,4},{2,3,4}};

// ------------------------------ PTX helpers ---------------------------------
__device__ __forceinline__ uint32_t smem_to_u32(const void* p) {
    uint32_t a;
    asm("{ .reg .u64 t; cvta.to.shared.u64 t, %1; cvt.u32.u64 %0, t; }" : "=r"(a) : "l"(p));
    return a;
}
__device__ __forceinline__ void cp_async16(uint32_t dst, const void* src) {
    asm volatile("cp.async.cg.shared.global [%0], [%1], 16;\n" :: "r"(dst), "l"(src));
}
__device__ __forceinline__ void cp_commit() {
    asm volatile("cp.async.commit_group;\n" ::: "memory");
}
template <int N>
__device__ __forceinline__ void cp_wait() {
    asm volatile("cp.async.wait_group %0;\n" :: "n"(N) : "memory");
}
__device__ __forceinline__ void ldm4(uint32_t (&r)[4], uint32_t a) {
    asm volatile("ldmatrix.sync.aligned.m8n8.x4.shared.b16 {%0,%1,%2,%3}, [%4];"
                 : "=r"(r[0]), "=r"(r[1]), "=r"(r[2]), "=r"(r[3]) : "r"(a));
}
__device__ __forceinline__ void mma16816(float (&d)[4], const uint32_t (&a)[4],
                                         uint32_t b0, uint32_t b1) {
    asm volatile(
        "mma.sync.aligned.m16n8k16.row.col.f32.f16.f16.f32 "
        "{%0,%1,%2,%3}, {%4,%5,%6,%7}, {%8,%9}, {%0,%1,%2,%3};"
        : "+f"(d[0]), "+f"(d[1]), "+f"(d[2]), "+f"(d[3])
        : "r"(a[0]), "r"(a[1]), "r"(a[2]), "r"(a[3]), "r"(b0), "r"(b1));
}

// ----------------------------------------------------------------------------
// prep: 4 rows per block (256 threads), sort cards, gather embeddings -> fp16
// ----------------------------------------------------------------------------
__global__ void prep_kernel(const int* __restrict__ x, const float* __restrict__ emb,
                            __half* __restrict__ ah)
{
    int t  = threadIdx.x;
    int lr = t >> 6;
    int c  = t & 63;
    int m  = blockIdx.x * 4 + lr;

    __shared__ int   cid[4][9];
    __shared__ float e9[4][9][EMBD];

    if (c == 0) {
        int key[9], cc[9];
        #pragma unroll
        for (int i = 0; i < 9; i++) {
            int rk = x[m * 18 + 2 * i];
            int st = x[m * 18 + 2 * i + 1];
            key[i] = rk * 8 + st;
            cc[i]  = (rk - 1) * st;
        }
        for (int i = 1; i < 4; i++) {
            int k = key[i], v = cc[i], j = i - 1;
            while (j >= 0 && key[j] > k) { key[j+1] = key[j]; cc[j+1] = cc[j]; j--; }
            key[j+1] = k; cc[j+1] = v;
        }
        for (int i = 5; i < 9; i++) {
            int k = key[i], v = cc[i], j = i - 1;
            while (j >= 4 && key[j] > k) { key[j+1] = key[j]; cc[j+1] = cc[j]; j--; }
            key[j+1] = k; cc[j+1] = v;
        }
        #pragma unroll
        for (int i = 0; i < 9; i++) cid[lr][i] = cc[i];
    }
    __syncthreads();

    #pragma unroll
    for (int i = 0; i < 9; i++) e9[lr][i][c] = emb[cid[lr][i] * EMBD + c];

    #pragma unroll
    for (int hh = 0; hh < 6; hh++) {
        size_t base = A_HEROIN + ((size_t)m * 6 + hh) * 128;
        ah[base + c]      = __float2half_rn(e9[lr][HP[hh][0]][c]);
        ah[base + 64 + c] = __float2half_rn(e9[lr][HP[hh][1]][c]);
    }
    #pragma unroll
    for (int b = 0; b < 10; b++) {
        size_t base = A_BOARDIN + ((size_t)m * 10 + b) * 192;
        ah[base + c]       = __float2half_rn(e9[lr][4 + BT[b][0]][c]);
        ah[base + 64 + c]  = __float2half_rn(e9[lr][4 + BT[b][1]][c]);
        ah[base + 128 + c] = __float2half_rn(e9[lr][4 + BT[b][2]][c]);
    }
}

// ----------------------------------------------------------------------------
// prep_w: z<6 -> transpose+fp16 weight; z==6 -> fused fold of oW1 into W_WF
// ----------------------------------------------------------------------------
struct TD { const float* src; __half* dh; int K, N, Npad; };
struct TDArr { TD d[6]; };

__global__ void prep_w_kernel(TDArr descs, const float* __restrict__ oW1,
                              __half* __restrict__ whBase)
{
    int tx = threadIdx.x, ty = threadIdx.y;
    if (blockIdx.z == 6) {
        int r0 = blockIdx.x * 32, n0 = blockIdx.y * 32;
        __shared__ float t[32][33];
        #pragma unroll
        for (int j = 0; j < 4; j++) {
            int r = r0 + ty + 8 * j;
            int n = n0 + tx;
            float s = 0.f;
            if (r < 768) {
                int h = r >> 7, k = r & 127;
                #pragma unroll
                for (int b = 0; b < 10; b++)
                    s += oW1[((size_t)((h * 10 + b) * 256 + k)) * 512 + n];
            } else {
                int rb = r - 768;
                int b = rb >> 7, k = rb & 127;
                #pragma unroll
                for (int h = 0; h < 6; h++)
                    s += oW1[((size_t)((h * 10 + b) * 256 + 128 + k)) * 512 + n];
            }
            t[ty + 8 * j][tx] = s;
        }
        __syncthreads();
        #pragma unroll
        for (int j = 0; j < 4; j++) {
            int nl = ty + 8 * j;
            whBase[W_WF + (size_t)(n0 + nl) * 2048 + r0 + tx] = __float2half_rn(t[tx][nl]);
        }
    } else {
        TD d = descs.d[blockIdx.z];
        int kt = blockIdx.x * 32, nt = blockIdx.y * 32;
        if (kt >= d.K || nt >= d.Npad) return;
        __shared__ float tile[32][33];
        for (int i = ty; i < 32; i += 8) {
            int k = kt + i, n = nt + tx;
            float v = (k < d.K && n < d.N) ? d.src[(size_t)k * d.N + n] : 0.f;
            tile[i][tx] = v;
        }
        __syncthreads();
        for (int i = ty; i < 32; i += 8) {
            int n = nt + i, k = kt + tx;
            if (n < d.Npad && k < d.K)
                d.dh[(size_t)n * d.K + k] = __float2half_rn(tile[tx][i]);
        }
    }
}

// ----------------------------------------------------------------------------
// HMMA GEMM, 128 threads (4 warps), BN=128, BK=32, 3-stage cp.async ring.
// BM=64: 2Mx2N warps (32x64 each); BM=32: 1Mx4N (32x32); BM=16: 1Mx4N (16x32).
// FINAL: fuse o3 epilogue + 127->9 scorer (writes fp32 out).
// ----------------------------------------------------------------------------
struct GemmP {
    const __half* Ah; const __half* Bh;
    const float* bias; int nbias;
    __half* Ch; float* Cp;
    int Kst;      // row stride of A and B (full K)
    int kcnt;     // K elements this CTA processes
    int divv, ldOut, seg, yb;
    size_t pstride;
    const float* sW; const float* sb; float* outp;
};

template<int BM, bool FINAL>
__global__ void __launch_bounds__(128, 4) hmma_gemm(GemmP p0, GemmP p1)
{
    constexpr int ROWB = 80;              // 32 fp16 (64B) + 16B pad
    constexpr int SA = BM * ROWB;
    constexpr int SB = 128 * ROWB;
    constexpr int STG = SA + SB;
    constexpr int MW = (BM >= 64) ? 2 : 1;   // M-warps
    constexpr int NWARP = 4 / MW;            // N-warps
    constexpr int WN = 128 / NWARP;          // cols per warp
    constexpr int NF = WN / 8;               // n8 frags per warp
    constexpr int WROWS = BM / MW;           // rows per warp (32 or 16)
    constexpr int MF = WROWS / 16;           // 16-row frags per warp (2 or 1)

    bool first = (blockIdx.y < (unsigned)p0.yb);
    GemmP p = first ? p0 : p1;
    int my = first ? blockIdx.y : (blockIdx.y - p0.yb);

    extern __shared__ char smem[];
    uint32_t sbase = smem_to_u32(smem);

    int tid = threadIdx.x, lane = tid & 31, wid = tid >> 5;
    int wy = wid / NWARP, wx = wid % NWARP;
    int m0 = my * BM, n0 = blockIdx.x * 128;
    int Kst = p.Kst;
    int kbeg = blockIdx.z * p.kcnt;

    // FINAL: stage sW/sb into smem beyond the pipeline region
    float* sWs = reinterpret_cast<float*>(smem + 3 * STG);
    float* sbs = sWs + 1143;
    if (FINAL) {
        for (int i = tid; i < 1143; i += 128) sWs[i] = p.sW[i];
        if (tid < 9) sbs[tid] = p.sb[tid];
    }

    float acc[MF][NF][4];
    #pragma unroll
    for (int i = 0; i < MF; i++)
        #pragma unroll
        for (int j = 0; j < NF; j++)
            #pragma unroll
            for (int q = 0; q < 4; q++) acc[i][j][q] = 0.f;

    auto load_stage = [&](int k0, int st) {
        uint32_t s0 = sbase + (uint32_t)st * STG;
        #pragma unroll
        for (int i = tid; i < BM * 4; i += 128) {
            int row = i >> 2, c = i & 3;
            size_t go = (size_t)(m0 + row) * Kst + kbeg + k0 + c * 8;
            cp_async16(s0 + row * ROWB + c * 16, p.Ah + go);
        }
        #pragma unroll
        for (int i = tid; i < 512; i += 128) {
            int row = i >> 2, c = i & 3;
            size_t go = (size_t)(n0 + row) * Kst + kbeg + k0 + c * 8;
            cp_async16(s0 + SA + row * ROWB + c * 16, p.Bh + go);
        }
    };

    uint32_t a_off = (uint32_t)((wy * WROWS + (lane & 15)) * ROWB + (lane >> 4) * 16);
    uint32_t b_off = (uint32_t)(SA + (wx * WN + (lane & 7)) * ROWB + ((lane >> 3) & 3) * 16);

    int nch = p.kcnt >> 5;
    load_stage(0, 0);
    cp_commit();
    if (nch > 1) load_stage(32, 1);
    cp_commit();

    for (int ch = 0; ch < nch; ch++) {
        cp_wait<1>();
        __syncthreads();
        if (ch + 2 < nch) load_stage((ch + 2) << 5, (ch + 2) % 3);
        cp_commit();

        uint32_t s0 = sbase + (uint32_t)(ch % 3) * STG;

        uint32_t bf[NF][4];
        #pragma unroll
        for (int ni = 0; ni < NF; ni++)
            ldm4(bf[ni], s0 + b_off + ni * (8 * ROWB));

        #pragma unroll
        for (int k16 = 0; k16 < 2; k16++) {
            #pragma unroll
            for (int mi = 0; mi < MF; mi++) {
                uint32_t af[4];
                ldm4(af, s0 + a_off + mi * (16 * ROWB) + k16 * 32);
                #pragma unroll
                for (int ni = 0; ni < NF; ni++)
                    mma16816(acc[mi][ni], af, bf[ni][2 * k16], bf[ni][2 * k16 + 1]);
            }
        }
    }

    if (FINAL) {
        // o3 epilogue (bias + lrelu) into smem tile, then fused 127->9 scorer
        float* sm = reinterpret_cast<float*>(smem);      // [BM][132]
        __syncthreads();                                  // all reads of stages done
        #pragma unroll
        for (int mi = 0; mi < MF; mi++) {
            #pragma unroll
            for (int ni = 0; ni < NF; ni++) {
                int n = wx * WN + ni * 8 + 2 * (lane & 3);
                float bv0 = (n < p.nbias) ? p.bias[n] : 0.f;
                float bv1 = (n + 1 < p.nbias) ? p.bias[n + 1] : 0.f;
                #pragma unroll
                for (int half = 0; half < 2; half++) {
                    int r = wy * WROWS + mi * 16 + (lane >> 2) + half * 8;
                    float v0 = acc[mi][ni][half * 2 + 0] + bv0;
                    float v1 = acc[mi][ni][half * 2 + 1] + bv1;
                    v0 = (v0 > 0.f) ? v0 : 0.01f * v0;
                    v1 = (v1 > 0.f) ? v1 : 0.01f * v1;
                    sm[r * 132 + n] = v0;
                    sm[r * 132 + n + 1] = v1;
                }
            }
        }
        __syncthreads();
        for (int idx = tid; idx < BM * 9; idx += 128) {
            int r = idx / 9, n = idx - r * 9;
            float a = sbs[n];
            #pragma unroll 1
            for (int k = 0; k < 127; k++) a += sm[r * 132 + k] * sWs[k * 9 + n];
            p.outp[(size_t)(m0 + r) * 9 + n] = a;
        }
        return;
    }

    // ---- standard epilogue ----
    #pragma unroll
    for (int mi = 0; mi < MF; mi++) {
        #pragma unroll
        for (int ni = 0; ni < NF; ni++) {
            int n = n0 + wx * WN + ni * 8 + 2 * (lane & 3);
            #pragma unroll
            for (int half = 0; half < 2; half++) {
                int r = m0 + wy * WROWS + mi * 16 + (lane >> 2) + half * 8;
                float v0 = acc[mi][ni][half * 2 + 0];
                float v1 = acc[mi][ni][half * 2 + 1];
                if (p.Cp) {
                    *reinterpret_cast<float2*>(p.Cp + blockIdx.z * p.pstride
                        + (size_t)r * p.ldOut + n) = make_float2(v0, v1);
                } else {
                    float bv0 = (n < p.nbias) ? p.bias[n] : 0.f;
                    float bv1 = (n + 1 < p.nbias) ? p.bias[n + 1] : 0.f;
                    v0 += bv0; v1 += bv1;
                    v0 = (v0 > 0.f) ? v0 : 0.01f * v0;
                    v1 = (v1 > 0.f) ? v1 : 0.01f * v1;
                    size_t base;
                    if (p.divv == 0) base = (size_t)r * p.ldOut + n;
                    else base = (size_t)(r / p.divv) * p.ldOut + p.seg
                              + (size_t)(r % p.divv) * 128 + n;
                    *reinterpret_cast<__half2*>(p.Ch + base) = __floats2half2_rn(v0, v1);
                }
            }
        }
    }
}

// ----------------------------------------------------------------------------
// reduce for o1 split-K=2: O1 = lrelu(p0+p1 + bias) -> fp16, 4 elems/thread
// ----------------------------------------------------------------------------
__global__ void reduce_o1_kernel(const float* __restrict__ Cp, const float* __restrict__ bias,
                                 __half* __restrict__ O1, size_t pstride, int total4)
{
    int i4 = blockIdx.x * 256 + threadIdx.x;
    if (i4 >= total4) return;
    int i = i4 * 4;
    float4 a = *reinterpret_cast<const float4*>(Cp + i);
    float4 b = *reinterpret_cast<const float4*>(Cp + pstride + i);
    int nb = i & 511;
    float v0 = a.x + b.x + bias[nb + 0];
    float v1 = a.y + b.y + bias[nb + 1];
    float v2 = a.z + b.z + bias[nb + 2];
    float v3 = a.w + b.w + bias[nb + 3];
    v0 = (v0 > 0.f) ? v0 : 0.01f * v0;
    v1 = (v1 > 0.f) ? v1 : 0.01f * v1;
    v2 = (v2 > 0.f) ? v2 : 0.01f * v2;
    v3 = (v3 > 0.f) ? v3 : 0.01f * v3;
    __half2 h0 = __floats2half2_rn(v0, v1);
    __half2 h1 = __floats2half2_rn(v2, v3);
    uint2 pk = make_uint2(*reinterpret_cast<uint32_t*>(&h0),
                          *reinterpret_cast<uint32_t*>(&h1));
    *reinterpret_cast<uint2*>(O1 + i) = pk;
}

// ----------------------------------------------------------------------------
extern "C" void kernel_launch(void* const* d_in, const int* in_sizes, int n_in,
                              void* d_out, int out_size)
{
    const int*   x   = (const int*)  d_in[0];
    const float* emb = (const float*)d_in[1];
    const float* hW1 = (const float*)d_in[2];
    const float* hb1 = (const float*)d_in[3];
    const float* hW2 = (const float*)d_in[4];
    const float* hb2 = (const float*)d_in[5];
    const float* bW1 = (const float*)d_in[6];
    const float* bb1 = (const float*)d_in[7];
    const float* bW2 = (const float*)d_in[8];
    const float* bb2 = (const float*)d_in[9];
    const float* oW1 = (const float*)d_in[10];
    const float* ob1 = (const float*)d_in[11];
    const float* oW2 = (const float*)d_in[12];
    const float* ob2 = (const float*)d_in[13];
    const float* oW3 = (const float*)d_in[14];
    const float* ob3 = (const float*)d_in[15];
    const float* sW  = (const float*)d_in[16];
    const float* sb  = (const float*)d_in[17];
    float* out = (float*)d_out;

    int M = in_sizes[0] / 18;
    if (M > MAXM) M = MAXM;

    __half *ah = nullptr, *wh = nullptr;
    float* part = nullptr;
    cudaGetSymbolAddress((void**)&ah, g_ah);
    cudaGetSymbolAddress((void**)&wh, g_wh);
    cudaGetSymbolAddress((void**)&part, g_part);

    constexpr int SMEM64 = 3 * (64 + 128) * 80;             // 46080
    constexpr int SMEM32 = 3 * (32 + 128) * 80;             // 38400
    constexpr int SMEM16 = 3 * (16 + 128) * 80;             // 34560
    constexpr int SMEMF  = SMEM16 + 1152 * 4 + 64;          // + sW/sb staging
    cudaFuncSetAttribute((const void*)hmma_gemm<64, false>,
                         cudaFuncAttributeMaxDynamicSharedMemorySize, SMEM64);
    cudaFuncSetAttribute((const void*)hmma_gemm<32, false>,
                         cudaFuncAttributeMaxDynamicSharedMemorySize, SMEM32);
    cudaFuncSetAttribute((const void*)hmma_gemm<16, false>,
                         cudaFuncAttributeMaxDynamicSharedMemorySize, SMEM16);
    cudaFuncSetAttribute((const void*)hmma_gemm<16, true>,
                         cudaFuncAttributeMaxDynamicSharedMemorySize, SMEMF);

    prep_kernel<<<M / 4, 256>>>(x, emb, ah);

    TDArr td;
    td.d[0] = { hW1, wh + W_HW1, 128, 512, 512 };
    td.d[1] = { hW2, wh + W_HW2, 512, 128, 128 };
    td.d[2] = { bW1, wh + W_BW1, 192, 512, 512 };
    td.d[3] = { bW2, wh + W_BW2, 512, 128, 128 };
    td.d[4] = { oW2, wh + W_OW2, 512, 256, 256 };
    td.d[5] = { oW3, wh + W_OW3, 256, 127, 128 };
    prep_w_kernel<<<dim3(64, 16, 7), dim3(32, 8)>>>(td, oW1, wh);

    int yh = (6 * M) / 64, yb = (10 * M) / 64;   // 192, 320

    // layer1 merged: hero [6M x 512, K=128], board [10M x 512, K=192]
    {
        GemmP ph = { ah + A_HEROIN, wh + W_HW1, hb1, 512, ah + A_HEROH, nullptr,
                     128, 128, 0, 512, 0, yh, 0, nullptr, nullptr, nullptr };
        GemmP pb = { ah + A_BOARDIN, wh + W_BW1, bb1, 512, ah + A_BOARDH, nullptr,
                     192, 192, 0, 512, 0, yb, 0, nullptr, nullptr, nullptr };
        hmma_gemm<64, false><<<dim3(4, yh + yb), 128, SMEM64>>>(ph, pb);
    }
    // layer2 merged: hero/board [.. x 128, K=512] -> X scatter
    {
        GemmP ph = { ah + A_HEROH, wh + W_HW2, hb2, 128, ah + A_X, nullptr,
                     512, 512, 6, 2048, 0, yh, 0, nullptr, nullptr, nullptr };
        GemmP pb = { ah + A_BOARDH, wh + W_BW2, bb2, 128, ah + A_X, nullptr,
                     512, 512, 10, 2048, 768, yb, 0, nullptr, nullptr, nullptr };
        hmma_gemm<64, false><<<dim3(1, yh + yb), 128, SMEM64>>>(ph, pb);
    }
    // o1: [M x 512], K=2048, split-K=2, BM=32, fp32 partials (512 CTAs)
    {
        GemmP p = { ah + A_X, wh + W_WF, nullptr, 0, nullptr, part,
                    2048, 1024, 0, 512, 0, M / 32, (size_t)M * 512,
                    nullptr, nullptr, nullptr };
        hmma_gemm<32, false><<<dim3(4, M / 32, 2), 128, SMEM32>>>(p, p);
        int total4 = (M * 512) / 4;
        reduce_o1_kernel<<<(total4 + 255) / 256, 256>>>(part, ob1, ah + A_O1,
                                                        (size_t)M * 512, total4);
    }
    // o2: [M x 256], K=512, BM=16 (256 CTAs)
    {
        GemmP p = { ah + A_O1, wh + W_OW2, ob2, 256, ah + A_O2, nullptr,
                    512, 512, 0, 256, 0, M / 16, 0, nullptr, nullptr, nullptr };
        hmma_gemm<16, false><<<dim3(2, M / 16), 128, SMEM16>>>(p, p);
    }
    // o3 + fused scorer: [M x 127] @ oW3 then 127->9, BM=16 (128 CTAs)
    {
        GemmP p = { ah + A_O2, wh + W_OW3, ob3, 127, nullptr, nullptr,
                    256, 256, 0, 128, 0, M / 16, 0, sW, sb, out };
        hmma_gemm<16, true><<<dim3(1, M / 16), 128, SMEMF>>>(p, p);
    }

    (void)out_size; (void)n_in;
}